// round 1
// baseline (speedup 1.0000x reference)
#include <cuda_runtime.h>
#include <cuda_bf16.h>
#include <math.h>

// ---------------------------------------------------------------------------
// Problem constants
// ---------------------------------------------------------------------------
#define T_TOK  1024
#define HID    1024
#define NH     16
#define NKV    4
#define HD     64
#define QKV_N  1536          // (NH + 2*NKV) * HD
#define NE     64
#define NG     8
#define INTER  512
#define NA     (T_TOK*NG)    // 8192 expert-assignments (exactly one per token per group)

// ---------------------------------------------------------------------------
// Scratch (static device globals -- no runtime allocation allowed)
// ---------------------------------------------------------------------------
__device__ float g_h   [T_TOK*HID];       // rmsnorm(hidden)
__device__ float g_qkv [T_TOK*QKV_N];     // qkv projection
__device__ float g_q   [T_TOK*NH*HD];     // roped+normed q
__device__ float g_k   [T_TOK*NKV*HD];    // roped+normed k
__device__ float g_attn[T_TOK*NH*HD];     // attention output
__device__ float g_h2  [T_TOK*HID];       // rmsnorm(post-attn)
__device__ float g_gu  [NA*1024];         // gate_up output (compact rows)
__device__ float g_act [NA*INTER];        // silu(g)*u*w (compact rows)
__device__ int   g_cnt [NE];
__device__ int   g_off [NE];
__device__ int   g_fill[NE];
__device__ int   g_selid[NA];
__device__ float g_selw [NA];
__device__ int   g_tok  [NA];             // compact token list (counting sort)
__device__ float g_w    [NA];             // per-assignment routing weight

// ---------------------------------------------------------------------------
// RMSNorm over rows of [T, HID]
// ---------------------------------------------------------------------------
__global__ void k_rmsnorm(const float* __restrict__ in,
                          const float* __restrict__ w,
                          float* __restrict__ out) {
    int t = blockIdx.x;
    const float* x = in + (size_t)t * HID;
    float ss = 0.f;
    for (int i = threadIdx.x; i < HID; i += 256) { float v = x[i]; ss += v * v; }
#pragma unroll
    for (int o = 16; o; o >>= 1) ss += __shfl_xor_sync(0xffffffffu, ss, o);
    __shared__ float red[8];
    __shared__ float stot;
    if ((threadIdx.x & 31) == 0) red[threadIdx.x >> 5] = ss;
    __syncthreads();
    if (threadIdx.x == 0) {
        float s = 0.f;
#pragma unroll
        for (int i = 0; i < 8; i++) s += red[i];
        stot = rsqrtf(s * (1.f / HID) + 1e-6f);
    }
    __syncthreads();
    float sc = stot;
    float* op = out + (size_t)t * HID;
    for (int i = threadIdx.x; i < HID; i += 256) op[i] = x[i] * sc * w[i];
}

// ---------------------------------------------------------------------------
// Generic fp32 SIMT GEMM: C[M,N] = A[M,K] @ B[K,N] (+ optional residual R[M,N])
// Tiles: 64x64x16, 256 threads, 4x4 per thread. All dims multiples of 64/16.
// ---------------------------------------------------------------------------
__global__ void k_gemm(const float* __restrict__ A, const float* __restrict__ B,
                       float* __restrict__ C, const float* __restrict__ R,
                       int M, int N, int K) {
    __shared__ float As[16][65];
    __shared__ float Bs[16][64];
    int tid = threadIdx.x;
    int tx = tid & 15, ty = tid >> 4;
    int m0 = blockIdx.y * 64, n0 = blockIdx.x * 64;
    int ar = tid >> 4, ac = tid & 15;
    float acc[4][4] = {};
    for (int k0 = 0; k0 < K; k0 += 16) {
#pragma unroll
        for (int j = 0; j < 4; j++)
            As[ac][ar + j * 16] = A[(size_t)(m0 + ar + j * 16) * K + k0 + ac];
#pragma unroll
        for (int j = 0; j < 4; j++) {
            int idx = tid + j * 256, r = idx >> 6, c = idx & 63;
            Bs[r][c] = B[(size_t)(k0 + r) * N + n0 + c];
        }
        __syncthreads();
#pragma unroll
        for (int k = 0; k < 16; k++) {
            float a[4], b[4];
#pragma unroll
            for (int i = 0; i < 4; i++) a[i] = As[k][ty * 4 + i];
#pragma unroll
            for (int j = 0; j < 4; j++) b[j] = Bs[k][tx * 4 + j];
#pragma unroll
            for (int i = 0; i < 4; i++)
#pragma unroll
                for (int j = 0; j < 4; j++) acc[i][j] += a[i] * b[j];
        }
        __syncthreads();
    }
#pragma unroll
    for (int i = 0; i < 4; i++) {
        int r = m0 + ty * 4 + i;
#pragma unroll
        for (int j = 0; j < 4; j++) {
            int c = n0 + tx * 4 + j;
            float v = acc[i][j];
            if (R) v += R[(size_t)r * N + c];
            C[(size_t)r * N + c] = v;
        }
    }
}

// ---------------------------------------------------------------------------
// Per-head RMSNorm + RoPE for q (16 heads) and k (4 heads).
// grid (20, T), block 32. Thread i owns elements (i, i+32) of a D=64 head.
// ---------------------------------------------------------------------------
__global__ void k_qk_prep(const int* __restrict__ pos,
                          const float* __restrict__ qnw,
                          const float* __restrict__ knw) {
    int hh = blockIdx.x;
    int t  = blockIdx.y;
    int i  = threadIdx.x;
    const float* src; float* dst; const float* w;
    if (hh < NH) {
        src = g_qkv + (size_t)t * QKV_N + hh * HD;
        dst = g_q   + (size_t)t * (NH * HD) + hh * HD;
        w = qnw;
    } else {
        int kh = hh - NH;
        src = g_qkv + (size_t)t * QKV_N + NH * HD + kh * HD;
        dst = g_k   + (size_t)t * (NKV * HD) + kh * HD;
        w = knw;
    }
    float x1 = src[i], x2 = src[i + 32];
    float ss = x1 * x1 + x2 * x2;
#pragma unroll
    for (int o = 16; o; o >>= 1) ss += __shfl_xor_sync(0xffffffffu, ss, o);
    float sc = rsqrtf(ss * (1.f / 64.f) + 1e-6f);
    x1 *= sc * w[i];
    x2 *= sc * w[i + 32];
    float p = (float)pos[t];
    float inv = powf(10000.f, -(float)i * (1.f / 32.f));
    float f = p * inv;
    float c = cosf(f), s = sinf(f);
    dst[i]      = x1 * c - x2 * s;
    dst[i + 32] = x2 * c + x1 * s;
}

// ---------------------------------------------------------------------------
// Flash attention (causal, GQA). grid (16 q-tiles, 16 heads), 256 threads.
// BM=BN=D=64. Online softmax, 4x4 register tiles, dynamic smem = 66560 B.
// ---------------------------------------------------------------------------
__global__ void k_attn() {
    extern __shared__ float sm[];
    const int LD = 65;
    float* Qs = sm;
    float* Ks = sm + 64 * LD;
    float* Vs = sm + 2 * 64 * LD;
    float* Ps = sm + 3 * 64 * LD;
    int h  = blockIdx.y;
    int m0 = blockIdx.x * 64;
    int kvh = h >> 2;
    int tid = threadIdx.x;
    int tx = tid & 15, ty = tid >> 4;
#pragma unroll
    for (int j = 0; j < 16; j++) {
        int idx = tid + j * 256;
        int r = idx >> 6, c = idx & 63;
        Qs[r * LD + c] = g_q[(size_t)(m0 + r) * (NH * HD) + h * HD + c];
    }
    float o[4][4] = {};
    float mrow[4], lrow[4];
#pragma unroll
    for (int i = 0; i < 4; i++) { mrow[i] = -INFINITY; lrow[i] = 0.f; }
    int ntiles = (m0 >> 6) + 1;
    for (int nt = 0; nt < ntiles; nt++) {
        int n0 = nt * 64;
        __syncthreads();
#pragma unroll
        for (int j = 0; j < 16; j++) {
            int idx = tid + j * 256;
            int r = idx >> 6, c = idx & 63;
            Ks[r * LD + c] = g_k[(size_t)(n0 + r) * (NKV * HD) + kvh * HD + c];
            Vs[r * LD + c] = g_qkv[(size_t)(n0 + r) * QKV_N + (NH + NKV) * HD + kvh * HD + c];
        }
        __syncthreads();
        float s[4][4] = {};
        for (int d = 0; d < 64; d++) {
            float a[4], b[4];
#pragma unroll
            for (int i = 0; i < 4; i++) a[i] = Qs[(ty * 4 + i) * LD + d];
#pragma unroll
            for (int j = 0; j < 4; j++) b[j] = Ks[(tx * 4 + j) * LD + d];
#pragma unroll
            for (int i = 0; i < 4; i++)
#pragma unroll
                for (int j = 0; j < 4; j++) s[i][j] += a[i] * b[j];
        }
#pragma unroll
        for (int i = 0; i < 4; i++) {
            int qi = m0 + ty * 4 + i;
#pragma unroll
            for (int j = 0; j < 4; j++) {
                float v = s[i][j] * 0.125f;
                if (n0 + tx * 4 + j > qi) v = -1e30f;
                s[i][j] = v;
            }
        }
#pragma unroll
        for (int i = 0; i < 4; i++) {
            float tm = fmaxf(fmaxf(s[i][0], s[i][1]), fmaxf(s[i][2], s[i][3]));
#pragma unroll
            for (int o2 = 1; o2 < 16; o2 <<= 1)
                tm = fmaxf(tm, __shfl_xor_sync(0xffffffffu, tm, o2));
            float mn = fmaxf(mrow[i], tm);
            float alpha = __expf(mrow[i] - mn);
            mrow[i] = mn;
            float ps = 0.f;
#pragma unroll
            for (int j = 0; j < 4; j++) {
                float p = __expf(s[i][j] - mn);
                Ps[(ty * 4 + i) * LD + tx * 4 + j] = p;
                ps += p;
            }
#pragma unroll
            for (int o2 = 1; o2 < 16; o2 <<= 1)
                ps += __shfl_xor_sync(0xffffffffu, ps, o2);
            lrow[i] = lrow[i] * alpha + ps;
#pragma unroll
            for (int j = 0; j < 4; j++) o[i][j] *= alpha;
        }
        __syncthreads();
        for (int n = 0; n < 64; n++) {
            float b[4];
#pragma unroll
            for (int j = 0; j < 4; j++) b[j] = Vs[n * LD + tx * 4 + j];
#pragma unroll
            for (int i = 0; i < 4; i++) {
                float p = Ps[(ty * 4 + i) * LD + n];
#pragma unroll
                for (int j = 0; j < 4; j++) o[i][j] += p * b[j];
            }
        }
    }
#pragma unroll
    for (int i = 0; i < 4; i++) {
        float inv = 1.f / lrow[i];
#pragma unroll
        for (int j = 0; j < 4; j++)
            g_attn[(size_t)(m0 + ty * 4 + i) * (NH * HD) + h * HD + tx * 4 + j] = o[i][j] * inv;
    }
}

// ---------------------------------------------------------------------------
// Routing: logits = h2 @ Wg; per group of 8, pick argmax; renormalize picks.
// (softmax denominator cancels, so route straight off logits)
// ---------------------------------------------------------------------------
__global__ void k_zero() {
    int i = threadIdx.x;
    if (i < NE) { g_cnt[i] = 0; g_fill[i] = 0; }
}

__global__ void k_route(const float* __restrict__ H2, const float* __restrict__ Wg) {
    int t = blockIdx.x;
    int e = threadIdx.x;  // 64 threads = 64 experts
    __shared__ float sh[HID];
    for (int i = e; i < HID; i += 64) sh[i] = H2[(size_t)t * HID + i];
    __syncthreads();
    float a0 = 0, a1 = 0, a2 = 0, a3 = 0;
    for (int k = 0; k < HID; k += 4) {
        a0 += sh[k]     * Wg[(size_t)k       * NE + e];
        a1 += sh[k + 1] * Wg[(size_t)(k + 1) * NE + e];
        a2 += sh[k + 2] * Wg[(size_t)(k + 2) * NE + e];
        a3 += sh[k + 3] * Wg[(size_t)(k + 3) * NE + e];
    }
    __shared__ float logits[NE];
    logits[e] = (a0 + a1) + (a2 + a3);
    __syncthreads();
    if (e == 0) {
        float sv[NG]; int si[NG];
#pragma unroll
        for (int g = 0; g < NG; g++) {
            float best = logits[g * 8]; int bi = g * 8;
#pragma unroll
            for (int j = 1; j < 8; j++) {
                float v = logits[g * 8 + j];
                if (v > best) { best = v; bi = g * 8 + j; }
            }
            sv[g] = best; si[g] = bi;
        }
        float m = sv[0];
#pragma unroll
        for (int g = 1; g < NG; g++) m = fmaxf(m, sv[g]);
        float sum = 0.f, p[NG];
#pragma unroll
        for (int g = 0; g < NG; g++) { p[g] = expf(sv[g] - m); sum += p[g]; }
        float is = 1.f / sum;
#pragma unroll
        for (int g = 0; g < NG; g++) {
            g_selid[t * NG + g] = si[g];
            g_selw [t * NG + g] = p[g] * is;
            atomicAdd(&g_cnt[si[g]], 1);
        }
    }
}

__global__ void k_scan() {  // 1 thread: exclusive scan over 64 counts
    int s = 0;
    for (int e = 0; e < NE; e++) { g_off[e] = s; s += g_cnt[e]; }
}

__global__ void k_scatter() {  // grid T, block 8: counting-sort scatter
    int t = blockIdx.x, g = threadIdx.x;
    int e = g_selid[t * NG + g];
    int slot = atomicAdd(&g_fill[e], 1);
    int row = g_off[e] + slot;
    g_tok[row] = t;
    g_w[row]   = g_selw[t * NG + g];
}

// ---------------------------------------------------------------------------
// MoE GEMM 1: gu[row, :1024] = h2[tok[row], :] @ W_gate_up[e]  (gathered A)
// grid (16 Ntiles, 16 Mtiles, 64 experts); blocks past count[e] exit.
// ---------------------------------------------------------------------------
__global__ void k_moe_gemm1(const float* __restrict__ H2, const float* __restrict__ Wgu) {
    int e = blockIdx.z;
    int cnt = g_cnt[e];
    int m0 = blockIdx.y * 64;
    if (m0 >= cnt) return;
    int off = g_off[e];
    int n0 = blockIdx.x * 64;
    const float* B = Wgu + (size_t)e * (HID * 2 * INTER);
    __shared__ float As[16][65];
    __shared__ float Bs[16][64];
    int tid = threadIdx.x, tx = tid & 15, ty = tid >> 4;
    int ar = tid >> 4, ac = tid & 15;
    int tok[4]; bool val[4];
#pragma unroll
    for (int j = 0; j < 4; j++) {
        int r = ar + j * 16;
        val[j] = (m0 + r) < cnt;
        tok[j] = val[j] ? g_tok[off + m0 + r] : 0;
    }
    float acc[4][4] = {};
    for (int k0 = 0; k0 < HID; k0 += 16) {
#pragma unroll
        for (int j = 0; j < 4; j++)
            As[ac][ar + j * 16] = val[j] ? H2[(size_t)tok[j] * HID + k0 + ac] : 0.f;
#pragma unroll
        for (int j = 0; j < 4; j++) {
            int idx = tid + j * 256, r = idx >> 6, c = idx & 63;
            Bs[r][c] = B[(size_t)(k0 + r) * 1024 + n0 + c];
        }
        __syncthreads();
#pragma unroll
        for (int k = 0; k < 16; k++) {
            float a[4], b[4];
#pragma unroll
            for (int i = 0; i < 4; i++) a[i] = As[k][ty * 4 + i];
#pragma unroll
            for (int j = 0; j < 4; j++) b[j] = Bs[k][tx * 4 + j];
#pragma unroll
            for (int i = 0; i < 4; i++)
#pragma unroll
                for (int j = 0; j < 4; j++) acc[i][j] += a[i] * b[j];
        }
        __syncthreads();
    }
#pragma unroll
    for (int i = 0; i < 4; i++) {
        int r = m0 + ty * 4 + i;
        if (r < cnt) {
#pragma unroll
            for (int j = 0; j < 4; j++)
                g_gu[(size_t)(off + r) * 1024 + n0 + tx * 4 + j] = acc[i][j];
        }
    }
}

// act[row, i] = silu(gu[row, i]) * gu[row, 512+i] * w[row]
__global__ void k_moe_act() {
    int idx = blockIdx.x * 256 + threadIdx.x;
    int r = idx >> 9;
    int i = idx & 511;
    float g = g_gu[(size_t)r * 1024 + i];
    float u = g_gu[(size_t)r * 1024 + 512 + i];
    float s = g / (1.f + expf(-g));
    g_act[(size_t)r * INTER + i] = s * u * g_w[r];
}

// ---------------------------------------------------------------------------
// MoE GEMM 2: out[tok[row], :] += act[row, :512] @ W_down[e]  (scatter-add)
// ---------------------------------------------------------------------------
__global__ void k_moe_gemm2(const float* __restrict__ Wd, float* __restrict__ out) {
    int e = blockIdx.z;
    int cnt = g_cnt[e];
    int m0 = blockIdx.y * 64;
    if (m0 >= cnt) return;
    int off = g_off[e];
    int n0 = blockIdx.x * 64;
    const float* B = Wd + (size_t)e * (INTER * HID);
    __shared__ float As[16][65];
    __shared__ float Bs[16][64];
    int tid = threadIdx.x, tx = tid & 15, ty = tid >> 4;
    int ar = tid >> 4, ac = tid & 15;
    float acc[4][4] = {};
    for (int k0 = 0; k0 < INTER; k0 += 16) {
#pragma unroll
        for (int j = 0; j < 4; j++) {
            int r = ar + j * 16;
            As[ac][r] = ((m0 + r) < cnt) ? g_act[(size_t)(off + m0 + r) * INTER + k0 + ac] : 0.f;
        }
#pragma unroll
        for (int j = 0; j < 4; j++) {
            int idx = tid + j * 256, r = idx >> 6, c = idx & 63;
            Bs[r][c] = B[(size_t)(k0 + r) * HID + n0 + c];
        }
        __syncthreads();
#pragma unroll
        for (int k = 0; k < 16; k++) {
            float a[4], b[4];
#pragma unroll
            for (int i = 0; i < 4; i++) a[i] = As[k][ty * 4 + i];
#pragma unroll
            for (int j = 0; j < 4; j++) b[j] = Bs[k][tx * 4 + j];
#pragma unroll
            for (int i = 0; i < 4; i++)
#pragma unroll
                for (int j = 0; j < 4; j++) acc[i][j] += a[i] * b[j];
        }
        __syncthreads();
    }
#pragma unroll
    for (int i = 0; i < 4; i++) {
        int r = m0 + ty * 4 + i;
        if (r < cnt) {
            int tokr = g_tok[off + r];
#pragma unroll
            for (int j = 0; j < 4; j++)
                atomicAdd(&out[(size_t)tokr * HID + n0 + tx * 4 + j], acc[i][j]);
        }
    }
}

// ---------------------------------------------------------------------------
// Launch
// ---------------------------------------------------------------------------
extern "C" void kernel_launch(void* const* d_in, const int* in_sizes, int n_in,
                              void* d_out, int out_size) {
    const int*   positions = (const int*)  d_in[0];
    const float* hidden    = (const float*)d_in[1];
    const float* Wqkv      = (const float*)d_in[2];
    const float* Wo        = (const float*)d_in[3];
    const float* qnw       = (const float*)d_in[4];
    const float* knw       = (const float*)d_in[5];
    const float* inln      = (const float*)d_in[6];
    const float* postln    = (const float*)d_in[7];
    const float* Wg        = (const float*)d_in[8];
    const float* Wgu       = (const float*)d_in[9];
    const float* Wd        = (const float*)d_in[10];
    float* out = (float*)d_out;

    float *p_h, *p_qkv, *p_h2, *p_attn;
    cudaGetSymbolAddress((void**)&p_h,    g_h);
    cudaGetSymbolAddress((void**)&p_qkv,  g_qkv);
    cudaGetSymbolAddress((void**)&p_h2,   g_h2);
    cudaGetSymbolAddress((void**)&p_attn, g_attn);

    const int ATTN_SMEM = 4 * 64 * 65 * 4;  // 66560 B
    cudaFuncSetAttribute(k_attn, cudaFuncAttributeMaxDynamicSharedMemorySize, ATTN_SMEM);

    // 1. pre-attn rmsnorm
    k_rmsnorm<<<T_TOK, 256>>>(hidden, inln, p_h);
    // 2. qkv projection
    k_gemm<<<dim3(QKV_N / 64, T_TOK / 64), 256>>>(p_h, Wqkv, p_qkv, nullptr,
                                                  T_TOK, QKV_N, HID);
    // 3. per-head rmsnorm + rope
    k_qk_prep<<<dim3(NH + NKV, T_TOK), 32>>>(positions, qnw, knw);
    // 4. causal flash attention
    k_attn<<<dim3(T_TOK / 64, NH), 256, ATTN_SMEM>>>();
    // 5. x = resid + attn @ Wo   (written to d_out)
    k_gemm<<<dim3(HID / 64, T_TOK / 64), 256>>>(p_attn, Wo, out, hidden,
                                                T_TOK, HID, NH * HD);
    // 6. post-attn rmsnorm
    k_rmsnorm<<<T_TOK, 256>>>(out, postln, p_h2);
    // 7-10. routing (counting sort into compact per-expert token lists)
    k_zero<<<1, 64>>>();
    k_route<<<T_TOK, 64>>>(p_h2, Wg);
    k_scan<<<1, 1>>>();
    k_scatter<<<T_TOK, 8>>>();
    // 11. grouped gate_up GEMM
    k_moe_gemm1<<<dim3(16, 16, NE), 256>>>(p_h2, Wgu);
    // 12. silu(g)*u*w
    k_moe_act<<<(NA * INTER) / 256, 256>>>();
    // 13. grouped down GEMM, scatter-add into d_out
    k_moe_gemm2<<<dim3(16, 16, NE), 256>>>(Wd, out);
}

// round 2
// speedup vs baseline: 1.1387x; 1.1387x over previous
#include <cuda_runtime.h>
#include <cuda_bf16.h>
#include <mma.h>
#include <math.h>

using namespace nvcuda;

// ---------------------------------------------------------------------------
// Problem constants
// ---------------------------------------------------------------------------
#define T_TOK  1024
#define HID    1024
#define NH     16
#define NKV    4
#define HD     64
#define QKV_N  1536
#define NE     64
#define NG     8
#define INTER  512
#define NA     (T_TOK*NG)
#define NA_PAD 16384          // 8192 assignments + up to 64*127 padding, rounded

// GEMM tiling
#define BM 128
#define BN 128
#define BK 16
#define LDA 24                // padded smem ld for A tile (mult of 8)
#define LDB 136               // padded smem ld for B tile (mult of 8)

// ---------------------------------------------------------------------------
// Scratch (static device globals -- no runtime allocation allowed)
// ---------------------------------------------------------------------------
__device__ float g_h   [T_TOK*HID];
__device__ float g_qkv [T_TOK*QKV_N];
__device__ float g_q   [T_TOK*NH*HD];
__device__ float g_k   [T_TOK*NKV*HD];
__device__ float g_attn[T_TOK*NH*HD];
__device__ float g_h2  [T_TOK*HID];
__device__ float g_gu  [NA_PAD*1024];
__device__ float g_act [NA_PAD*INTER];
__device__ int   g_cnt [NE];
__device__ int   g_off [NE];       // padded exclusive scan (multiples of 128)
__device__ int   g_fill[NE];
__device__ int   g_selid[NA];
__device__ float g_selw [NA];
__device__ int   g_tok  [NA_PAD];
__device__ float g_w    [NA_PAD];

// ---------------------------------------------------------------------------
// RMSNorm
// ---------------------------------------------------------------------------
__global__ void k_rmsnorm(const float* __restrict__ in,
                          const float* __restrict__ w,
                          float* __restrict__ out) {
    int t = blockIdx.x;
    const float* x = in + (size_t)t * HID;
    float ss = 0.f;
    for (int i = threadIdx.x; i < HID; i += 256) { float v = x[i]; ss += v * v; }
#pragma unroll
    for (int o = 16; o; o >>= 1) ss += __shfl_xor_sync(0xffffffffu, ss, o);
    __shared__ float red[8];
    __shared__ float stot;
    if ((threadIdx.x & 31) == 0) red[threadIdx.x >> 5] = ss;
    __syncthreads();
    if (threadIdx.x == 0) {
        float s = 0.f;
#pragma unroll
        for (int i = 0; i < 8; i++) s += red[i];
        stot = rsqrtf(s * (1.f / HID) + 1e-6f);
    }
    __syncthreads();
    float sc = stot;
    float* op = out + (size_t)t * HID;
    for (int i = threadIdx.x; i < HID; i += 256) op[i] = x[i] * sc * w[i];
}

// ---------------------------------------------------------------------------
// tf32 WMMA tile core helpers
// ---------------------------------------------------------------------------
using FragA = wmma::fragment<wmma::matrix_a, 16, 16, 8, wmma::precision::tf32, wmma::row_major>;
using FragB = wmma::fragment<wmma::matrix_b, 16, 16, 8, wmma::precision::tf32, wmma::row_major>;
using FragC = wmma::fragment<wmma::accumulator, 16, 16, 8, float>;

__device__ __forceinline__ void mma_step(const float* As, const float* Bs,
                                         FragC acc[2][4], int wm, int wn) {
#pragma unroll
    for (int kk = 0; kk < BK; kk += 8) {
        FragA af[2];
        FragB bf[4];
#pragma unroll
        for (int i = 0; i < 2; i++) {
            wmma::load_matrix_sync(af[i], As + (wm * 32 + i * 16) * LDA + kk, LDA);
#pragma unroll
            for (int t = 0; t < af[i].num_elements; t++)
                af[i].x[t] = wmma::__float_to_tf32(af[i].x[t]);
        }
#pragma unroll
        for (int j = 0; j < 4; j++) {
            wmma::load_matrix_sync(bf[j], Bs + kk * LDB + wn * 64 + j * 16, LDB);
#pragma unroll
            for (int t = 0; t < bf[j].num_elements; t++)
                bf[j].x[t] = wmma::__float_to_tf32(bf[j].x[t]);
        }
#pragma unroll
        for (int i = 0; i < 2; i++)
#pragma unroll
            for (int j = 0; j < 4; j++)
                wmma::mma_sync(acc[i][j], af[i], bf[j], acc[i][j]);
    }
}

// ---------------------------------------------------------------------------
// Dense GEMM: C[M,N] = A[M,K] @ B[K,N] (+ optional residual R)
// ---------------------------------------------------------------------------
__global__ void k_gemm_tf32(const float* __restrict__ A, const float* __restrict__ B,
                            float* __restrict__ C, const float* __restrict__ R,
                            int M, int N, int K) {
    __shared__ float As[BM * LDA];
    __shared__ float Bs[BK * LDB];
    int tid = threadIdx.x;
    int warp = tid >> 5;
    int wm = warp >> 1, wn = warp & 1;
    int m0 = blockIdx.y * BM, n0 = blockIdx.x * BN;

    FragC acc[2][4];
    if (R) {
#pragma unroll
        for (int i = 0; i < 2; i++)
#pragma unroll
            for (int j = 0; j < 4; j++)
                wmma::load_matrix_sync(acc[i][j],
                    R + (size_t)(m0 + wm * 32 + i * 16) * N + n0 + wn * 64 + j * 16,
                    N, wmma::mem_row_major);
    } else {
#pragma unroll
        for (int i = 0; i < 2; i++)
#pragma unroll
            for (int j = 0; j < 4; j++) wmma::fill_fragment(acc[i][j], 0.f);
    }

    for (int k0 = 0; k0 < K; k0 += BK) {
#pragma unroll
        for (int j = 0; j < 2; j++) {
            int l = tid + j * 256;
            int r = l >> 2, c4 = l & 3;
            *(float4*)&As[r * LDA + c4 * 4] =
                *(const float4*)&A[(size_t)(m0 + r) * K + k0 + c4 * 4];
        }
#pragma unroll
        for (int j = 0; j < 2; j++) {
            int l = tid + j * 256;
            int r = l >> 5, c4 = l & 31;
            *(float4*)&Bs[r * LDB + c4 * 4] =
                *(const float4*)&B[(size_t)(k0 + r) * N + n0 + c4 * 4];
        }
        __syncthreads();
        mma_step(As, Bs, acc, wm, wn);
        __syncthreads();
    }
#pragma unroll
    for (int i = 0; i < 2; i++)
#pragma unroll
        for (int j = 0; j < 4; j++)
            wmma::store_matrix_sync(
                C + (size_t)(m0 + wm * 32 + i * 16) * N + n0 + wn * 64 + j * 16,
                acc[i][j], N, wmma::mem_row_major);
}

// ---------------------------------------------------------------------------
// Per-head RMSNorm + RoPE
// ---------------------------------------------------------------------------
__global__ void k_qk_prep(const int* __restrict__ pos,
                          const float* __restrict__ qnw,
                          const float* __restrict__ knw) {
    int hh = blockIdx.x;
    int t  = blockIdx.y;
    int i  = threadIdx.x;
    const float* src; float* dst; const float* w;
    if (hh < NH) {
        src = g_qkv + (size_t)t * QKV_N + hh * HD;
        dst = g_q   + (size_t)t * (NH * HD) + hh * HD;
        w = qnw;
    } else {
        int kh = hh - NH;
        src = g_qkv + (size_t)t * QKV_N + NH * HD + kh * HD;
        dst = g_k   + (size_t)t * (NKV * HD) + kh * HD;
        w = knw;
    }
    float x1 = src[i], x2 = src[i + 32];
    float ss = x1 * x1 + x2 * x2;
#pragma unroll
    for (int o = 16; o; o >>= 1) ss += __shfl_xor_sync(0xffffffffu, ss, o);
    float sc = rsqrtf(ss * (1.f / 64.f) + 1e-6f);
    x1 *= sc * w[i];
    x2 *= sc * w[i + 32];
    float p = (float)pos[t];
    float inv = powf(10000.f, -(float)i * (1.f / 32.f));
    float f = p * inv;
    float c = cosf(f), s = sinf(f);
    dst[i]      = x1 * c - x2 * s;
    dst[i + 32] = x2 * c + x1 * s;
}

// ---------------------------------------------------------------------------
// Flash attention (causal, GQA) -- unchanged fp32 SIMT this round
// ---------------------------------------------------------------------------
__global__ void k_attn() {
    extern __shared__ float sm[];
    const int LD = 65;
    float* Qs = sm;
    float* Ks = sm + 64 * LD;
    float* Vs = sm + 2 * 64 * LD;
    float* Ps = sm + 3 * 64 * LD;
    int h  = blockIdx.y;
    int m0 = blockIdx.x * 64;
    int kvh = h >> 2;
    int tid = threadIdx.x;
    int tx = tid & 15, ty = tid >> 4;
#pragma unroll
    for (int j = 0; j < 16; j++) {
        int idx = tid + j * 256;
        int r = idx >> 6, c = idx & 63;
        Qs[r * LD + c] = g_q[(size_t)(m0 + r) * (NH * HD) + h * HD + c];
    }
    float o[4][4] = {};
    float mrow[4], lrow[4];
#pragma unroll
    for (int i = 0; i < 4; i++) { mrow[i] = -INFINITY; lrow[i] = 0.f; }
    int ntiles = (m0 >> 6) + 1;
    for (int nt = 0; nt < ntiles; nt++) {
        int n0 = nt * 64;
        __syncthreads();
#pragma unroll
        for (int j = 0; j < 16; j++) {
            int idx = tid + j * 256;
            int r = idx >> 6, c = idx & 63;
            Ks[r * LD + c] = g_k[(size_t)(n0 + r) * (NKV * HD) + kvh * HD + c];
            Vs[r * LD + c] = g_qkv[(size_t)(n0 + r) * QKV_N + (NH + NKV) * HD + kvh * HD + c];
        }
        __syncthreads();
        float s[4][4] = {};
        for (int d = 0; d < 64; d++) {
            float a[4], b[4];
#pragma unroll
            for (int i = 0; i < 4; i++) a[i] = Qs[(ty * 4 + i) * LD + d];
#pragma unroll
            for (int j = 0; j < 4; j++) b[j] = Ks[(tx * 4 + j) * LD + d];
#pragma unroll
            for (int i = 0; i < 4; i++)
#pragma unroll
                for (int j = 0; j < 4; j++) s[i][j] += a[i] * b[j];
        }
#pragma unroll
        for (int i = 0; i < 4; i++) {
            int qi = m0 + ty * 4 + i;
#pragma unroll
            for (int j = 0; j < 4; j++) {
                float v = s[i][j] * 0.125f;
                if (n0 + tx * 4 + j > qi) v = -1e30f;
                s[i][j] = v;
            }
        }
#pragma unroll
        for (int i = 0; i < 4; i++) {
            float tm = fmaxf(fmaxf(s[i][0], s[i][1]), fmaxf(s[i][2], s[i][3]));
#pragma unroll
            for (int o2 = 1; o2 < 16; o2 <<= 1)
                tm = fmaxf(tm, __shfl_xor_sync(0xffffffffu, tm, o2));
            float mn = fmaxf(mrow[i], tm);
            float alpha = __expf(mrow[i] - mn);
            mrow[i] = mn;
            float ps = 0.f;
#pragma unroll
            for (int j = 0; j < 4; j++) {
                float p = __expf(s[i][j] - mn);
                Ps[(ty * 4 + i) * LD + tx * 4 + j] = p;
                ps += p;
            }
#pragma unroll
            for (int o2 = 1; o2 < 16; o2 <<= 1)
                ps += __shfl_xor_sync(0xffffffffu, ps, o2);
            lrow[i] = lrow[i] * alpha + ps;
#pragma unroll
            for (int j = 0; j < 4; j++) o[i][j] *= alpha;
        }
        __syncthreads();
        for (int n = 0; n < 64; n++) {
            float b[4];
#pragma unroll
            for (int j = 0; j < 4; j++) b[j] = Vs[n * LD + tx * 4 + j];
#pragma unroll
            for (int i = 0; i < 4; i++) {
                float p = Ps[(ty * 4 + i) * LD + n];
#pragma unroll
                for (int j = 0; j < 4; j++) o[i][j] += p * b[j];
            }
        }
    }
#pragma unroll
    for (int i = 0; i < 4; i++) {
        float inv = 1.f / lrow[i];
#pragma unroll
        for (int j = 0; j < 4; j++)
            g_attn[(size_t)(m0 + ty * 4 + i) * (NH * HD) + h * HD + tx * 4 + j] = o[i][j] * inv;
    }
}

// ---------------------------------------------------------------------------
// Routing
// ---------------------------------------------------------------------------
__global__ void k_zero() {
    int i = threadIdx.x;
    if (i < NE) { g_cnt[i] = 0; g_fill[i] = 0; }
}

__global__ void k_route(const float* __restrict__ H2, const float* __restrict__ Wg) {
    int t = blockIdx.x;
    int e = threadIdx.x;
    __shared__ float sh[HID];
    for (int i = e; i < HID; i += 64) sh[i] = H2[(size_t)t * HID + i];
    __syncthreads();
    float a0 = 0, a1 = 0, a2 = 0, a3 = 0;
    for (int k = 0; k < HID; k += 4) {
        a0 += sh[k]     * Wg[(size_t)k       * NE + e];
        a1 += sh[k + 1] * Wg[(size_t)(k + 1) * NE + e];
        a2 += sh[k + 2] * Wg[(size_t)(k + 2) * NE + e];
        a3 += sh[k + 3] * Wg[(size_t)(k + 3) * NE + e];
    }
    __shared__ float logits[NE];
    logits[e] = (a0 + a1) + (a2 + a3);
    __syncthreads();
    if (e == 0) {
        float sv[NG]; int si[NG];
#pragma unroll
        for (int g = 0; g < NG; g++) {
            float best = logits[g * 8]; int bi = g * 8;
#pragma unroll
            for (int j = 1; j < 8; j++) {
                float v = logits[g * 8 + j];
                if (v > best) { best = v; bi = g * 8 + j; }
            }
            sv[g] = best; si[g] = bi;
        }
        float m = sv[0];
#pragma unroll
        for (int g = 1; g < NG; g++) m = fmaxf(m, sv[g]);
        float sum = 0.f, p[NG];
#pragma unroll
        for (int g = 0; g < NG; g++) { p[g] = expf(sv[g] - m); sum += p[g]; }
        float is = 1.f / sum;
#pragma unroll
        for (int g = 0; g < NG; g++) {
            g_selid[t * NG + g] = si[g];
            g_selw [t * NG + g] = p[g] * is;
            atomicAdd(&g_cnt[si[g]], 1);
        }
    }
}

__global__ void k_scan() {  // padded exclusive scan (multiples of BM)
    int s = 0;
    for (int e = 0; e < NE; e++) { g_off[e] = s; s += (g_cnt[e] + BM - 1) & ~(BM - 1); }
}

__global__ void k_scatter() {
    int t = blockIdx.x, g = threadIdx.x;
    int e = g_selid[t * NG + g];
    int slot = atomicAdd(&g_fill[e], 1);
    int row = g_off[e] + slot;
    g_tok[row] = t;
    g_w[row]   = g_selw[t * NG + g];
}

// ---------------------------------------------------------------------------
// MoE GEMM 1 (tf32): gu[rows of expert e] = H2[tok] @ Wgu[e]
// Padded regions: rows >= cnt get A=0 -> gu=0, stored unguarded in padding.
// ---------------------------------------------------------------------------
__global__ void k_moe1_tf32(const float* __restrict__ H2, const float* __restrict__ Wgu) {
    int e = blockIdx.z;
    int cnt = g_cnt[e];
    int m0 = blockIdx.y * BM;
    if (m0 >= cnt) return;
    int off = g_off[e];
    int n0 = blockIdx.x * BN;
    const float* B = Wgu + (size_t)e * (HID * 1024);

    __shared__ float As[BM * LDA];
    __shared__ float Bs[BK * LDB];
    __shared__ int stok[BM];
    int tid = threadIdx.x;
    int warp = tid >> 5;
    int wm = warp >> 1, wn = warp & 1;
    if (tid < BM) stok[tid] = (m0 + tid < cnt) ? g_tok[off + m0 + tid] : -1;
    __syncthreads();

    FragC acc[2][4];
#pragma unroll
    for (int i = 0; i < 2; i++)
#pragma unroll
        for (int j = 0; j < 4; j++) wmma::fill_fragment(acc[i][j], 0.f);

    for (int k0 = 0; k0 < HID; k0 += BK) {
#pragma unroll
        for (int j = 0; j < 2; j++) {
            int l = tid + j * 256;
            int r = l >> 2, c4 = l & 3;
            int tk = stok[r];
            float4 v = make_float4(0.f, 0.f, 0.f, 0.f);
            if (tk >= 0) v = *(const float4*)&H2[(size_t)tk * HID + k0 + c4 * 4];
            *(float4*)&As[r * LDA + c4 * 4] = v;
        }
#pragma unroll
        for (int j = 0; j < 2; j++) {
            int l = tid + j * 256;
            int r = l >> 5, c4 = l & 31;
            *(float4*)&Bs[r * LDB + c4 * 4] =
                *(const float4*)&B[(size_t)(k0 + r) * 1024 + n0 + c4 * 4];
        }
        __syncthreads();
        mma_step(As, Bs, acc, wm, wn);
        __syncthreads();
    }
#pragma unroll
    for (int i = 0; i < 2; i++)
#pragma unroll
        for (int j = 0; j < 4; j++)
            wmma::store_matrix_sync(
                g_gu + (size_t)(off + m0 + wm * 32 + i * 16) * 1024 + n0 + wn * 64 + j * 16,
                acc[i][j], 1024, wmma::mem_row_major);
}

// act[row,i] = silu(gu[row,i]) * gu[row,512+i] * w[row]
__global__ void k_moe_act() {
    int idx = blockIdx.x * 256 + threadIdx.x;
    int r = idx >> 9;
    int i = idx & 511;
    float g = g_gu[(size_t)r * 1024 + i];
    float u = g_gu[(size_t)r * 1024 + 512 + i];
    float s = g / (1.f + __expf(-g));
    g_act[(size_t)r * INTER + i] = s * u * g_w[r];
}

// ---------------------------------------------------------------------------
// MoE GEMM 2 (tf32): out[tok[row]] += act[row] @ Wd[e]  (staged scatter-add)
// ---------------------------------------------------------------------------
__global__ void k_moe2_tf32(const float* __restrict__ Wd, float* __restrict__ out) {
    int e = blockIdx.z;
    int cnt = g_cnt[e];
    int m0 = blockIdx.y * BM;
    if (m0 >= cnt) return;
    int off = g_off[e];
    int n0 = blockIdx.x * BN;
    const float* B = Wd + (size_t)e * (INTER * HID);

    __shared__ float As[BM * LDA];
    __shared__ float Bs[BK * LDB];
    __shared__ float stage[8 * 272];
    __shared__ int stok[BM];
    int tid = threadIdx.x;
    int lane = tid & 31;
    int warp = tid >> 5;
    int wm = warp >> 1, wn = warp & 1;
    if (tid < BM) stok[tid] = (m0 + tid < cnt) ? g_tok[off + m0 + tid] : -1;
    __syncthreads();

    FragC acc[2][4];
#pragma unroll
    for (int i = 0; i < 2; i++)
#pragma unroll
        for (int j = 0; j < 4; j++) wmma::fill_fragment(acc[i][j], 0.f);

    for (int k0 = 0; k0 < INTER; k0 += BK) {
#pragma unroll
        for (int j = 0; j < 2; j++) {
            int l = tid + j * 256;
            int r = l >> 2, c4 = l & 3;
            // padding rows of g_act contain zeros -> safe unguarded load
            *(float4*)&As[r * LDA + c4 * 4] =
                *(const float4*)&g_act[(size_t)(off + m0 + r) * INTER + k0 + c4 * 4];
        }
#pragma unroll
        for (int j = 0; j < 2; j++) {
            int l = tid + j * 256;
            int r = l >> 5, c4 = l & 31;
            *(float4*)&Bs[r * LDB + c4 * 4] =
                *(const float4*)&B[(size_t)(k0 + r) * HID + n0 + c4 * 4];
        }
        __syncthreads();
        mma_step(As, Bs, acc, wm, wn);
        __syncthreads();
    }

    // Staged scatter-add epilogue
#pragma unroll
    for (int i = 0; i < 2; i++) {
#pragma unroll
        for (int j = 0; j < 4; j++) {
            wmma::store_matrix_sync(&stage[warp * 272], acc[i][j], 16, wmma::mem_row_major);
            __syncwarp();
#pragma unroll
            for (int q = 0; q < 8; q++) {
                int el = lane + q * 32;
                int r = el >> 4, c = el & 15;
                int lr = wm * 32 + i * 16 + r;
                if (m0 + lr < cnt) {
                    int tk = stok[lr];
                    atomicAdd(&out[(size_t)tk * HID + n0 + wn * 64 + j * 16 + c],
                              stage[warp * 272 + r * 16 + c]);
                }
            }
            __syncwarp();
        }
    }
}

// ---------------------------------------------------------------------------
// Launch
// ---------------------------------------------------------------------------
extern "C" void kernel_launch(void* const* d_in, const int* in_sizes, int n_in,
                              void* d_out, int out_size) {
    const int*   positions = (const int*)  d_in[0];
    const float* hidden    = (const float*)d_in[1];
    const float* Wqkv      = (const float*)d_in[2];
    const float* Wo        = (const float*)d_in[3];
    const float* qnw       = (const float*)d_in[4];
    const float* knw       = (const float*)d_in[5];
    const float* inln      = (const float*)d_in[6];
    const float* postln    = (const float*)d_in[7];
    const float* Wg        = (const float*)d_in[8];
    const float* Wgu       = (const float*)d_in[9];
    const float* Wd        = (const float*)d_in[10];
    float* out = (float*)d_out;

    float *p_h, *p_qkv, *p_h2, *p_attn;
    cudaGetSymbolAddress((void**)&p_h,    g_h);
    cudaGetSymbolAddress((void**)&p_qkv,  g_qkv);
    cudaGetSymbolAddress((void**)&p_h2,   g_h2);
    cudaGetSymbolAddress((void**)&p_attn, g_attn);

    const int ATTN_SMEM = 4 * 64 * 65 * 4;
    cudaFuncSetAttribute(k_attn, cudaFuncAttributeMaxDynamicSharedMemorySize, ATTN_SMEM);

    // 1. pre-attn rmsnorm
    k_rmsnorm<<<T_TOK, 256>>>(hidden, inln, p_h);
    // 2. qkv projection (tf32)
    k_gemm_tf32<<<dim3(QKV_N / BN, T_TOK / BM), 256>>>(p_h, Wqkv, p_qkv, nullptr,
                                                       T_TOK, QKV_N, HID);
    // 3. per-head rmsnorm + rope
    k_qk_prep<<<dim3(NH + NKV, T_TOK), 32>>>(positions, qnw, knw);
    // 4. causal flash attention
    k_attn<<<dim3(T_TOK / 64, NH), 256, ATTN_SMEM>>>();
    // 5. x = resid + attn @ Wo (tf32, residual fused)
    k_gemm_tf32<<<dim3(HID / BN, T_TOK / BM), 256>>>(p_attn, Wo, out, hidden,
                                                     T_TOK, HID, NH * HD);
    // 6. post-attn rmsnorm
    k_rmsnorm<<<T_TOK, 256>>>(out, postln, p_h2);
    // 7-10. routing
    k_zero<<<1, 64>>>();
    k_route<<<T_TOK, 64>>>(p_h2, Wg);
    k_scan<<<1, 1>>>();
    k_scatter<<<T_TOK, 8>>>();
    // 11. grouped gate_up GEMM (tf32)
    k_moe1_tf32<<<dim3(1024 / BN, 8, NE), 256>>>(p_h2, Wgu);
    // 12. silu(g)*u*w
    k_moe_act<<<(NA_PAD * INTER) / 256, 256>>>();
    // 13. grouped down GEMM (tf32, scatter-add)
    k_moe2_tf32<<<dim3(HID / BN, 8, NE), 256>>>(Wd, out);
}

// round 3
// speedup vs baseline: 2.4718x; 2.1707x over previous
#include <cuda_runtime.h>
#include <cuda_bf16.h>
#include <mma.h>
#include <math.h>

using namespace nvcuda;

// ---------------------------------------------------------------------------
// Problem constants
// ---------------------------------------------------------------------------
#define T_TOK  1024
#define HID    1024
#define NH     16
#define NKV    4
#define HD     64
#define QKV_N  1536
#define NE     64
#define NG     8
#define INTER  512
#define NA     (T_TOK*NG)
#define NA_PAD 16384

// GEMM tiling
#define BM 128
#define BN 128
#define BK 32
#define LDA_S 40     // smem ld for A tile (bf16 elems)
#define LDB_S 136    // smem ld for B tile (bf16 elems)

// ---------------------------------------------------------------------------
// Scratch (static device globals)
// ---------------------------------------------------------------------------
__device__ __nv_bfloat16 g_hb   [T_TOK*HID];     // rmsnorm(hidden) bf16
__device__ float         g_qkv  [T_TOK*QKV_N];   // qkv projection fp32
__device__ float         g_q    [T_TOK*NH*HD];
__device__ float         g_k    [T_TOK*NKV*HD];
__device__ __nv_bfloat16 g_attnb[T_TOK*NH*HD];   // attention out bf16
__device__ float         g_h2   [T_TOK*HID];     // post-ln fp32 (router)
__device__ __nv_bfloat16 g_h2b  [T_TOK*HID];     // post-ln bf16 (moe A)
__device__ float         g_gu   [NA_PAD*1024];
__device__ __nv_bfloat16 g_actb [NA_PAD*INTER];
__device__ int   g_cnt [NE];
__device__ int   g_off [NE];
__device__ int   g_fill[NE];
__device__ int   g_selid[NA];
__device__ float g_selw [NA];
__device__ int   g_tok  [NA_PAD];
__device__ float g_w    [NA_PAD];

// ---------------------------------------------------------------------------
// WMMA types + helpers
// ---------------------------------------------------------------------------
using FragA = wmma::fragment<wmma::matrix_a, 16, 16, 16, __nv_bfloat16, wmma::row_major>;
using FragB = wmma::fragment<wmma::matrix_b, 16, 16, 16, __nv_bfloat16, wmma::row_major>;
using FragC = wmma::fragment<wmma::accumulator, 16, 16, 16, float>;

__device__ __forceinline__ uint4 f8_to_bf8(float4 a, float4 b) {
    __nv_bfloat162 p0 = __floats2bfloat162_rn(a.x, a.y);
    __nv_bfloat162 p1 = __floats2bfloat162_rn(a.z, a.w);
    __nv_bfloat162 p2 = __floats2bfloat162_rn(b.x, b.y);
    __nv_bfloat162 p3 = __floats2bfloat162_rn(b.z, b.w);
    uint4 r;
    r.x = *reinterpret_cast<unsigned*>(&p0);
    r.y = *reinterpret_cast<unsigned*>(&p1);
    r.z = *reinterpret_cast<unsigned*>(&p2);
    r.w = *reinterpret_cast<unsigned*>(&p3);
    return r;
}

__device__ __forceinline__ void mma_tile(const __nv_bfloat16* As, const __nv_bfloat16* Bs,
                                         FragC (&acc)[2][4], int wm, int wn) {
#pragma unroll
    for (int kk = 0; kk < BK; kk += 16) {
        FragA a[2];
        FragB b[4];
#pragma unroll
        for (int i = 0; i < 2; i++)
            wmma::load_matrix_sync(a[i], As + (wm * 32 + i * 16) * LDA_S + kk, LDA_S);
#pragma unroll
        for (int j = 0; j < 4; j++)
            wmma::load_matrix_sync(b[j], Bs + kk * LDB_S + wn * 64 + j * 16, LDB_S);
#pragma unroll
        for (int i = 0; i < 2; i++)
#pragma unroll
            for (int j = 0; j < 4; j++)
                wmma::mma_sync(acc[i][j], a[i], b[j], acc[i][j]);
    }
}

// ---------------------------------------------------------------------------
// RMSNorm (optional fp32 + bf16 outputs)
// ---------------------------------------------------------------------------
__global__ void k_rmsnorm(const float* __restrict__ in,
                          const float* __restrict__ w,
                          float* __restrict__ outf,
                          __nv_bfloat16* __restrict__ outb) {
    int t = blockIdx.x;
    const float* x = in + (size_t)t * HID;
    float ss = 0.f;
    for (int i = threadIdx.x; i < HID; i += 256) { float v = x[i]; ss += v * v; }
#pragma unroll
    for (int o = 16; o; o >>= 1) ss += __shfl_xor_sync(0xffffffffu, ss, o);
    __shared__ float red[8];
    __shared__ float stot;
    if ((threadIdx.x & 31) == 0) red[threadIdx.x >> 5] = ss;
    __syncthreads();
    if (threadIdx.x == 0) {
        float s = 0.f;
#pragma unroll
        for (int i = 0; i < 8; i++) s += red[i];
        stot = rsqrtf(s * (1.f / HID) + 1e-6f);
    }
    __syncthreads();
    float sc = stot;
    for (int i = threadIdx.x; i < HID; i += 256) {
        float v = x[i] * sc * w[i];
        if (outf) outf[(size_t)t * HID + i] = v;
        if (outb) outb[(size_t)t * HID + i] = __float2bfloat16(v);
    }
}

// ---------------------------------------------------------------------------
// Dense bf16 GEMM: C[M,N] = A_bf16[M,K] @ B_f32[K,N] (+ optional residual R)
// Double-buffered smem, reg-staged LDG->convert->STS, one sync per K-iter.
// ---------------------------------------------------------------------------
__global__ void __launch_bounds__(256) k_gemm_bf16(
        const __nv_bfloat16* __restrict__ A, const float* __restrict__ B,
        float* __restrict__ C, const float* __restrict__ R,
        int M, int N, int K) {
    __shared__ __nv_bfloat16 As[2][BM * LDA_S];
    __shared__ __nv_bfloat16 Bs[2][BK * LDB_S];
    int tid = threadIdx.x;
    int warp = tid >> 5;
    int wm = warp & 3, wn = warp >> 2;
    int m0 = blockIdx.y * BM, n0 = blockIdx.x * BN;

    // load coords
    int a_r = tid >> 2, a_c = (tid & 3) * 8;       // A: 2 chunks (rows a_r, a_r+64)
    int b_r = tid >> 4, b_c = (tid & 15) * 8;      // B: 2 chunks (rows b_r, b_r+16)

    FragC acc[2][4];
    if (R) {
#pragma unroll
        for (int i = 0; i < 2; i++)
#pragma unroll
            for (int j = 0; j < 4; j++)
                wmma::load_matrix_sync(acc[i][j],
                    R + (size_t)(m0 + wm * 32 + i * 16) * N + n0 + wn * 64 + j * 16,
                    N, wmma::mem_row_major);
    } else {
#pragma unroll
        for (int i = 0; i < 2; i++)
#pragma unroll
            for (int j = 0; j < 4; j++) wmma::fill_fragment(acc[i][j], 0.f);
    }

    uint4 ra0, ra1;
    float4 rb0a, rb0b, rb1a, rb1b;
    auto ldg = [&](int k0) {
        ra0 = *(const uint4*)&A[(size_t)(m0 + a_r) * K + k0 + a_c];
        ra1 = *(const uint4*)&A[(size_t)(m0 + a_r + 64) * K + k0 + a_c];
        const float* p0 = &B[(size_t)(k0 + b_r) * N + n0 + b_c];
        rb0a = *(const float4*)p0; rb0b = *(const float4*)(p0 + 4);
        const float* p1 = &B[(size_t)(k0 + b_r + 16) * N + n0 + b_c];
        rb1a = *(const float4*)p1; rb1b = *(const float4*)(p1 + 4);
    };
    auto sts = [&](int buf) {
        *(uint4*)&As[buf][a_r * LDA_S + a_c] = ra0;
        *(uint4*)&As[buf][(a_r + 64) * LDA_S + a_c] = ra1;
        *(uint4*)&Bs[buf][b_r * LDB_S + b_c] = f8_to_bf8(rb0a, rb0b);
        *(uint4*)&Bs[buf][(b_r + 16) * LDB_S + b_c] = f8_to_bf8(rb1a, rb1b);
    };

    int niter = K / BK;
    ldg(0); sts(0); __syncthreads();
    for (int it = 0; it < niter; it++) {
        if (it + 1 < niter) ldg((it + 1) * BK);
        mma_tile(As[it & 1], Bs[it & 1], acc, wm, wn);
        if (it + 1 < niter) { sts((it + 1) & 1); __syncthreads(); }
    }
#pragma unroll
    for (int i = 0; i < 2; i++)
#pragma unroll
        for (int j = 0; j < 4; j++)
            wmma::store_matrix_sync(
                C + (size_t)(m0 + wm * 32 + i * 16) * N + n0 + wn * 64 + j * 16,
                acc[i][j], N, wmma::mem_row_major);
}

// ---------------------------------------------------------------------------
// Per-head RMSNorm + RoPE
// ---------------------------------------------------------------------------
__global__ void k_qk_prep(const int* __restrict__ pos,
                          const float* __restrict__ qnw,
                          const float* __restrict__ knw) {
    int hh = blockIdx.x;
    int t  = blockIdx.y;
    int i  = threadIdx.x;
    const float* src; float* dst; const float* w;
    if (hh < NH) {
        src = g_qkv + (size_t)t * QKV_N + hh * HD;
        dst = g_q   + (size_t)t * (NH * HD) + hh * HD;
        w = qnw;
    } else {
        int kh = hh - NH;
        src = g_qkv + (size_t)t * QKV_N + NH * HD + kh * HD;
        dst = g_k   + (size_t)t * (NKV * HD) + kh * HD;
        w = knw;
    }
    float x1 = src[i], x2 = src[i + 32];
    float ss = x1 * x1 + x2 * x2;
#pragma unroll
    for (int o = 16; o; o >>= 1) ss += __shfl_xor_sync(0xffffffffu, ss, o);
    float sc = rsqrtf(ss * (1.f / 64.f) + 1e-6f);
    x1 *= sc * w[i];
    x2 *= sc * w[i + 32];
    float p = (float)pos[t];
    float inv = powf(10000.f, -(float)i * (1.f / 32.f));
    float f = p * inv;
    float c = cosf(f), s = sinf(f);
    dst[i]      = x1 * c - x2 * s;
    dst[i + 32] = x2 * c + x1 * s;
}

// ---------------------------------------------------------------------------
// Flash attention (causal, GQA) -- fp32 SIMT; epilogue writes bf16
// ---------------------------------------------------------------------------
__global__ void k_attn() {
    extern __shared__ float sm[];
    const int LD = 65;
    float* Qs = sm;
    float* Ks = sm + 64 * LD;
    float* Vs = sm + 2 * 64 * LD;
    float* Ps = sm + 3 * 64 * LD;
    int h  = blockIdx.y;
    int m0 = blockIdx.x * 64;
    int kvh = h >> 2;
    int tid = threadIdx.x;
    int tx = tid & 15, ty = tid >> 4;
#pragma unroll
    for (int j = 0; j < 16; j++) {
        int idx = tid + j * 256;
        int r = idx >> 6, c = idx & 63;
        Qs[r * LD + c] = g_q[(size_t)(m0 + r) * (NH * HD) + h * HD + c];
    }
    float o[4][4] = {};
    float mrow[4], lrow[4];
#pragma unroll
    for (int i = 0; i < 4; i++) { mrow[i] = -INFINITY; lrow[i] = 0.f; }
    int ntiles = (m0 >> 6) + 1;
    for (int nt = 0; nt < ntiles; nt++) {
        int n0 = nt * 64;
        __syncthreads();
#pragma unroll
        for (int j = 0; j < 16; j++) {
            int idx = tid + j * 256;
            int r = idx >> 6, c = idx & 63;
            Ks[r * LD + c] = g_k[(size_t)(n0 + r) * (NKV * HD) + kvh * HD + c];
            Vs[r * LD + c] = g_qkv[(size_t)(n0 + r) * QKV_N + (NH + NKV) * HD + kvh * HD + c];
        }
        __syncthreads();
        float s[4][4] = {};
        for (int d = 0; d < 64; d++) {
            float a[4], b[4];
#pragma unroll
            for (int i = 0; i < 4; i++) a[i] = Qs[(ty * 4 + i) * LD + d];
#pragma unroll
            for (int j = 0; j < 4; j++) b[j] = Ks[(tx * 4 + j) * LD + d];
#pragma unroll
            for (int i = 0; i < 4; i++)
#pragma unroll
                for (int j = 0; j < 4; j++) s[i][j] += a[i] * b[j];
        }
#pragma unroll
        for (int i = 0; i < 4; i++) {
            int qi = m0 + ty * 4 + i;
#pragma unroll
            for (int j = 0; j < 4; j++) {
                float v = s[i][j] * 0.125f;
                if (n0 + tx * 4 + j > qi) v = -1e30f;
                s[i][j] = v;
            }
        }
#pragma unroll
        for (int i = 0; i < 4; i++) {
            float tm = fmaxf(fmaxf(s[i][0], s[i][1]), fmaxf(s[i][2], s[i][3]));
#pragma unroll
            for (int o2 = 1; o2 < 16; o2 <<= 1)
                tm = fmaxf(tm, __shfl_xor_sync(0xffffffffu, tm, o2));
            float mn = fmaxf(mrow[i], tm);
            float alpha = __expf(mrow[i] - mn);
            mrow[i] = mn;
            float ps = 0.f;
#pragma unroll
            for (int j = 0; j < 4; j++) {
                float p = __expf(s[i][j] - mn);
                Ps[(ty * 4 + i) * LD + tx * 4 + j] = p;
                ps += p;
            }
#pragma unroll
            for (int o2 = 1; o2 < 16; o2 <<= 1)
                ps += __shfl_xor_sync(0xffffffffu, ps, o2);
            lrow[i] = lrow[i] * alpha + ps;
#pragma unroll
            for (int j = 0; j < 4; j++) o[i][j] *= alpha;
        }
        __syncthreads();
        for (int n = 0; n < 64; n++) {
            float b[4];
#pragma unroll
            for (int j = 0; j < 4; j++) b[j] = Vs[n * LD + tx * 4 + j];
#pragma unroll
            for (int i = 0; i < 4; i++) {
                float p = Ps[(ty * 4 + i) * LD + n];
#pragma unroll
                for (int j = 0; j < 4; j++) o[i][j] += p * b[j];
            }
        }
    }
#pragma unroll
    for (int i = 0; i < 4; i++) {
        float inv = 1.f / lrow[i];
#pragma unroll
        for (int j = 0; j < 4; j++)
            g_attnb[(size_t)(m0 + ty * 4 + i) * (NH * HD) + h * HD + tx * 4 + j] =
                __float2bfloat16(o[i][j] * inv);
    }
}

// ---------------------------------------------------------------------------
// Routing
// ---------------------------------------------------------------------------
__global__ void k_zero() {
    int i = threadIdx.x;
    if (i < NE) { g_cnt[i] = 0; g_fill[i] = 0; }
}

__global__ void k_route(const float* __restrict__ H2, const float* __restrict__ Wg) {
    int t = blockIdx.x;
    int e = threadIdx.x;
    __shared__ float sh[HID];
    for (int i = e; i < HID; i += 64) sh[i] = H2[(size_t)t * HID + i];
    __syncthreads();
    float a0 = 0, a1 = 0, a2 = 0, a3 = 0;
    for (int k = 0; k < HID; k += 4) {
        a0 += sh[k]     * Wg[(size_t)k       * NE + e];
        a1 += sh[k + 1] * Wg[(size_t)(k + 1) * NE + e];
        a2 += sh[k + 2] * Wg[(size_t)(k + 2) * NE + e];
        a3 += sh[k + 3] * Wg[(size_t)(k + 3) * NE + e];
    }
    __shared__ float logits[NE];
    logits[e] = (a0 + a1) + (a2 + a3);
    __syncthreads();
    if (e == 0) {
        float sv[NG]; int si[NG];
#pragma unroll
        for (int g = 0; g < NG; g++) {
            float best = logits[g * 8]; int bi = g * 8;
#pragma unroll
            for (int j = 1; j < 8; j++) {
                float v = logits[g * 8 + j];
                if (v > best) { best = v; bi = g * 8 + j; }
            }
            sv[g] = best; si[g] = bi;
        }
        float m = sv[0];
#pragma unroll
        for (int g = 1; g < NG; g++) m = fmaxf(m, sv[g]);
        float sum = 0.f, p[NG];
#pragma unroll
        for (int g = 0; g < NG; g++) { p[g] = expf(sv[g] - m); sum += p[g]; }
        float is = 1.f / sum;
#pragma unroll
        for (int g = 0; g < NG; g++) {
            g_selid[t * NG + g] = si[g];
            g_selw [t * NG + g] = p[g] * is;
            atomicAdd(&g_cnt[si[g]], 1);
        }
    }
}

__global__ void k_scan() {
    int s = 0;
    for (int e = 0; e < NE; e++) { g_off[e] = s; s += (g_cnt[e] + BM - 1) & ~(BM - 1); }
}

__global__ void k_scatter() {
    int t = blockIdx.x, g = threadIdx.x;
    int e = g_selid[t * NG + g];
    int slot = atomicAdd(&g_fill[e], 1);
    int row = g_off[e] + slot;
    g_tok[row] = t;
    g_w[row]   = g_selw[t * NG + g];
}

// ---------------------------------------------------------------------------
// MoE GEMM 1 (bf16): gu[rows of expert e] = H2b[tok] @ Wgu[e]; N=1024, K=HID
// ---------------------------------------------------------------------------
__global__ void __launch_bounds__(256) k_moe1(const __nv_bfloat16* __restrict__ Ab,
                                              const float* __restrict__ Wgu) {
    int e = blockIdx.z;
    int cnt = g_cnt[e];
    int m0 = blockIdx.y * BM;
    if (m0 >= cnt) return;
    int off = g_off[e];
    int n0 = blockIdx.x * BN;
    const float* B = Wgu + (size_t)e * (HID * 1024);

    __shared__ __nv_bfloat16 As[2][BM * LDA_S];
    __shared__ __nv_bfloat16 Bs[2][BK * LDB_S];
    __shared__ int stok[BM];
    int tid = threadIdx.x;
    int warp = tid >> 5;
    int wm = warp & 3, wn = warp >> 2;
    if (tid < BM) stok[tid] = (m0 + tid < cnt) ? g_tok[off + m0 + tid] : -1;
    __syncthreads();

    int a_r = tid >> 2, a_c = (tid & 3) * 8;
    int b_r = tid >> 4, b_c = (tid & 15) * 8;
    int tk0 = stok[a_r], tk1 = stok[a_r + 64];

    FragC acc[2][4];
#pragma unroll
    for (int i = 0; i < 2; i++)
#pragma unroll
        for (int j = 0; j < 4; j++) wmma::fill_fragment(acc[i][j], 0.f);

    uint4 ra0, ra1;
    float4 rb0a, rb0b, rb1a, rb1b;
    const uint4 Z = make_uint4(0, 0, 0, 0);
    auto ldg = [&](int k0) {
        ra0 = (tk0 >= 0) ? *(const uint4*)&Ab[(size_t)tk0 * HID + k0 + a_c] : Z;
        ra1 = (tk1 >= 0) ? *(const uint4*)&Ab[(size_t)tk1 * HID + k0 + a_c] : Z;
        const float* p0 = &B[(size_t)(k0 + b_r) * 1024 + n0 + b_c];
        rb0a = *(const float4*)p0; rb0b = *(const float4*)(p0 + 4);
        const float* p1 = &B[(size_t)(k0 + b_r + 16) * 1024 + n0 + b_c];
        rb1a = *(const float4*)p1; rb1b = *(const float4*)(p1 + 4);
    };
    auto sts = [&](int buf) {
        *(uint4*)&As[buf][a_r * LDA_S + a_c] = ra0;
        *(uint4*)&As[buf][(a_r + 64) * LDA_S + a_c] = ra1;
        *(uint4*)&Bs[buf][b_r * LDB_S + b_c] = f8_to_bf8(rb0a, rb0b);
        *(uint4*)&Bs[buf][(b_r + 16) * LDB_S + b_c] = f8_to_bf8(rb1a, rb1b);
    };

    const int niter = HID / BK;
    ldg(0); sts(0); __syncthreads();
    for (int it = 0; it < niter; it++) {
        if (it + 1 < niter) ldg((it + 1) * BK);
        mma_tile(As[it & 1], Bs[it & 1], acc, wm, wn);
        if (it + 1 < niter) { sts((it + 1) & 1); __syncthreads(); }
    }
#pragma unroll
    for (int i = 0; i < 2; i++)
#pragma unroll
        for (int j = 0; j < 4; j++)
            wmma::store_matrix_sync(
                g_gu + (size_t)(off + m0 + wm * 32 + i * 16) * 1024 + n0 + wn * 64 + j * 16,
                acc[i][j], 1024, wmma::mem_row_major);
}

// act[row,i] = silu(g)*u*w -> bf16
__global__ void k_moe_act() {
    int idx = blockIdx.x * 256 + threadIdx.x;   // one per 4 elems
    int r  = idx >> 7;
    int i4 = (idx & 127) * 4;
    float4 g = *(const float4*)&g_gu[(size_t)r * 1024 + i4];
    float4 u = *(const float4*)&g_gu[(size_t)r * 1024 + 512 + i4];
    float w = g_w[r];
    float s0 = g.x / (1.f + __expf(-g.x)) * u.x * w;
    float s1 = g.y / (1.f + __expf(-g.y)) * u.y * w;
    float s2 = g.z / (1.f + __expf(-g.z)) * u.z * w;
    float s3 = g.w / (1.f + __expf(-g.w)) * u.w * w;
    __nv_bfloat162 p0 = __floats2bfloat162_rn(s0, s1);
    __nv_bfloat162 p1 = __floats2bfloat162_rn(s2, s3);
    uint2 v;
    v.x = *reinterpret_cast<unsigned*>(&p0);
    v.y = *reinterpret_cast<unsigned*>(&p1);
    *(uint2*)&g_actb[(size_t)r * INTER + i4] = v;
}

// ---------------------------------------------------------------------------
// MoE GEMM 2 (bf16): out[tok[row]] += act[row] @ Wd[e]; N=HID, K=INTER
// ---------------------------------------------------------------------------
__global__ void __launch_bounds__(256) k_moe2(const float* __restrict__ Wd,
                                              float* __restrict__ out) {
    int e = blockIdx.z;
    int cnt = g_cnt[e];
    int m0 = blockIdx.y * BM;
    if (m0 >= cnt) return;
    int off = g_off[e];
    int n0 = blockIdx.x * BN;
    const float* B = Wd + (size_t)e * (INTER * HID);

    __shared__ __nv_bfloat16 As[2][BM * LDA_S];
    __shared__ __nv_bfloat16 Bs[2][BK * LDB_S];
    __shared__ float stage[8 * 272];
    __shared__ int stok[BM];
    int tid = threadIdx.x;
    int lane = tid & 31;
    int warp = tid >> 5;
    int wm = warp & 3, wn = warp >> 2;
    if (tid < BM) stok[tid] = (m0 + tid < cnt) ? g_tok[off + m0 + tid] : -1;
    __syncthreads();

    int a_r = tid >> 2, a_c = (tid & 3) * 8;
    int b_r = tid >> 4, b_c = (tid & 15) * 8;

    FragC acc[2][4];
#pragma unroll
    for (int i = 0; i < 2; i++)
#pragma unroll
        for (int j = 0; j < 4; j++) wmma::fill_fragment(acc[i][j], 0.f);

    uint4 ra0, ra1;
    float4 rb0a, rb0b, rb1a, rb1b;
    auto ldg = [&](int k0) {
        // padding rows of g_actb are zeros (moe1 computed them with A=0)
        ra0 = *(const uint4*)&g_actb[(size_t)(off + m0 + a_r) * INTER + k0 + a_c];
        ra1 = *(const uint4*)&g_actb[(size_t)(off + m0 + a_r + 64) * INTER + k0 + a_c];
        const float* p0 = &B[(size_t)(k0 + b_r) * HID + n0 + b_c];
        rb0a = *(const float4*)p0; rb0b = *(const float4*)(p0 + 4);
        const float* p1 = &B[(size_t)(k0 + b_r + 16) * HID + n0 + b_c];
        rb1a = *(const float4*)p1; rb1b = *(const float4*)(p1 + 4);
    };
    auto sts = [&](int buf) {
        *(uint4*)&As[buf][a_r * LDA_S + a_c] = ra0;
        *(uint4*)&As[buf][(a_r + 64) * LDA_S + a_c] = ra1;
        *(uint4*)&Bs[buf][b_r * LDB_S + b_c] = f8_to_bf8(rb0a, rb0b);
        *(uint4*)&Bs[buf][(b_r + 16) * LDB_S + b_c] = f8_to_bf8(rb1a, rb1b);
    };

    const int niter = INTER / BK;
    ldg(0); sts(0); __syncthreads();
    for (int it = 0; it < niter; it++) {
        if (it + 1 < niter) ldg((it + 1) * BK);
        mma_tile(As[it & 1], Bs[it & 1], acc, wm, wn);
        if (it + 1 < niter) { sts((it + 1) & 1); __syncthreads(); }
    }

    // staged scatter-add epilogue
#pragma unroll
    for (int i = 0; i < 2; i++) {
#pragma unroll
        for (int j = 0; j < 4; j++) {
            wmma::store_matrix_sync(&stage[warp * 272], acc[i][j], 16, wmma::mem_row_major);
            __syncwarp();
#pragma unroll
            for (int q = 0; q < 8; q++) {
                int el = lane + q * 32;
                int r = el >> 4, c = el & 15;
                int lr = wm * 32 + i * 16 + r;
                if (m0 + lr < cnt) {
                    int tk = stok[lr];
                    atomicAdd(&out[(size_t)tk * HID + n0 + wn * 64 + j * 16 + c],
                              stage[warp * 272 + r * 16 + c]);
                }
            }
            __syncwarp();
        }
    }
}

// ---------------------------------------------------------------------------
// Launch
// ---------------------------------------------------------------------------
extern "C" void kernel_launch(void* const* d_in, const int* in_sizes, int n_in,
                              void* d_out, int out_size) {
    const int*   positions = (const int*)  d_in[0];
    const float* hidden    = (const float*)d_in[1];
    const float* Wqkv      = (const float*)d_in[2];
    const float* Wo        = (const float*)d_in[3];
    const float* qnw       = (const float*)d_in[4];
    const float* knw       = (const float*)d_in[5];
    const float* inln      = (const float*)d_in[6];
    const float* postln    = (const float*)d_in[7];
    const float* Wg        = (const float*)d_in[8];
    const float* Wgu       = (const float*)d_in[9];
    const float* Wd        = (const float*)d_in[10];
    float* out = (float*)d_out;

    __nv_bfloat16 *p_hb, *p_attnb, *p_h2b;
    float *p_qkv, *p_h2;
    cudaGetSymbolAddress((void**)&p_hb,    g_hb);
    cudaGetSymbolAddress((void**)&p_qkv,   g_qkv);
    cudaGetSymbolAddress((void**)&p_h2,    g_h2);
    cudaGetSymbolAddress((void**)&p_h2b,   g_h2b);
    cudaGetSymbolAddress((void**)&p_attnb, g_attnb);

    const int ATTN_SMEM = 4 * 64 * 65 * 4;
    cudaFuncSetAttribute(k_attn, cudaFuncAttributeMaxDynamicSharedMemorySize, ATTN_SMEM);

    // 1. pre-attn rmsnorm (bf16 only)
    k_rmsnorm<<<T_TOK, 256>>>(hidden, inln, nullptr, p_hb);
    // 2. qkv projection
    k_gemm_bf16<<<dim3(QKV_N / BN, T_TOK / BM), 256>>>(p_hb, Wqkv, p_qkv, nullptr,
                                                       T_TOK, QKV_N, HID);
    // 3. per-head rmsnorm + rope
    k_qk_prep<<<dim3(NH + NKV, T_TOK), 32>>>(positions, qnw, knw);
    // 4. causal flash attention
    k_attn<<<dim3(T_TOK / 64, NH), 256, ATTN_SMEM>>>();
    // 5. x = resid + attn @ Wo
    k_gemm_bf16<<<dim3(HID / BN, T_TOK / BM), 256>>>(p_attnb, Wo, out, hidden,
                                                     T_TOK, HID, NH * HD);
    // 6. post-attn rmsnorm (fp32 for router + bf16 for MoE A)
    k_rmsnorm<<<T_TOK, 256>>>(out, postln, p_h2, p_h2b);
    // 7-10. routing
    k_zero<<<1, 64>>>();
    k_route<<<T_TOK, 64>>>(p_h2, Wg);
    k_scan<<<1, 1>>>();
    k_scatter<<<T_TOK, 8>>>();
    // 11. grouped gate_up GEMM
    k_moe1<<<dim3(1024 / BN, 8, NE), 256>>>(p_h2b, Wgu);
    // 12. silu(g)*u*w -> bf16
    k_moe_act<<<(NA_PAD * 128) / 256, 256>>>();
    // 13. grouped down GEMM, scatter-add into d_out
    k_moe2<<<dim3(HID / BN, 8, NE), 256>>>(Wd, out);
}

// round 4
// speedup vs baseline: 2.7453x; 1.1106x over previous
#include <cuda_runtime.h>
#include <cuda_bf16.h>
#include <mma.h>
#include <math.h>

using namespace nvcuda;

// ---------------------------------------------------------------------------
// Problem constants
// ---------------------------------------------------------------------------
#define T_TOK  1024
#define HID    1024
#define NH     16
#define NKV    4
#define HD     64
#define QKV_N  1536
#define NE     64
#define NG     8
#define INTER  512
#define NA     (T_TOK*NG)
#define NA_PAD 16384

// GEMM tiling
#define BM 128
#define BN 128
#define BK 32
#define LDA_S 40
#define LDB_S 136

// attention smem leading dims
#define LDH 72   // bf16 tiles
#define LDF 68   // fp32 tiles

// ---------------------------------------------------------------------------
// Scratch (static device globals)
// ---------------------------------------------------------------------------
__device__ __nv_bfloat16 g_hb   [T_TOK*HID];
__device__ float         g_qkv  [T_TOK*QKV_N];
__device__ __nv_bfloat16 g_qb   [T_TOK*NH*HD];
__device__ __nv_bfloat16 g_kb   [T_TOK*NKV*HD];
__device__ __nv_bfloat16 g_vb   [T_TOK*NKV*HD];
__device__ __nv_bfloat16 g_attnb[T_TOK*NH*HD];
__device__ float         g_h2   [T_TOK*HID];
__device__ __nv_bfloat16 g_h2b  [T_TOK*HID];
__device__ float         g_gu   [NA_PAD*1024];
__device__ __nv_bfloat16 g_actb [NA_PAD*INTER];
__device__ int   g_cnt [NE];
__device__ int   g_off [NE];
__device__ int   g_fill[NE];
__device__ int   g_selid[NA];
__device__ float g_selw [NA];
__device__ int   g_tok  [NA_PAD];
__device__ float g_w    [NA_PAD];

// ---------------------------------------------------------------------------
// WMMA types + helpers
// ---------------------------------------------------------------------------
using FragA  = wmma::fragment<wmma::matrix_a, 16, 16, 16, __nv_bfloat16, wmma::row_major>;
using FragB  = wmma::fragment<wmma::matrix_b, 16, 16, 16, __nv_bfloat16, wmma::row_major>;
using FragBc = wmma::fragment<wmma::matrix_b, 16, 16, 16, __nv_bfloat16, wmma::col_major>;
using FragC  = wmma::fragment<wmma::accumulator, 16, 16, 16, float>;

__device__ __forceinline__ uint4 f8_to_bf8(float4 a, float4 b) {
    __nv_bfloat162 p0 = __floats2bfloat162_rn(a.x, a.y);
    __nv_bfloat162 p1 = __floats2bfloat162_rn(a.z, a.w);
    __nv_bfloat162 p2 = __floats2bfloat162_rn(b.x, b.y);
    __nv_bfloat162 p3 = __floats2bfloat162_rn(b.z, b.w);
    uint4 r;
    r.x = *reinterpret_cast<unsigned*>(&p0);
    r.y = *reinterpret_cast<unsigned*>(&p1);
    r.z = *reinterpret_cast<unsigned*>(&p2);
    r.w = *reinterpret_cast<unsigned*>(&p3);
    return r;
}

__device__ __forceinline__ void mma_tile(const __nv_bfloat16* As, const __nv_bfloat16* Bs,
                                         FragC (&acc)[2][4], int wm, int wn) {
#pragma unroll
    for (int kk = 0; kk < BK; kk += 16) {
        FragA a[2];
        FragB b[4];
#pragma unroll
        for (int i = 0; i < 2; i++)
            wmma::load_matrix_sync(a[i], As + (wm * 32 + i * 16) * LDA_S + kk, LDA_S);
#pragma unroll
        for (int j = 0; j < 4; j++)
            wmma::load_matrix_sync(b[j], Bs + kk * LDB_S + wn * 64 + j * 16, LDB_S);
#pragma unroll
        for (int i = 0; i < 2; i++)
#pragma unroll
            for (int j = 0; j < 4; j++)
                wmma::mma_sync(acc[i][j], a[i], b[j], acc[i][j]);
    }
}

// ---------------------------------------------------------------------------
// RMSNorm
// ---------------------------------------------------------------------------
__global__ void k_rmsnorm(const float* __restrict__ in,
                          const float* __restrict__ w,
                          float* __restrict__ outf,
                          __nv_bfloat16* __restrict__ outb) {
    int t = blockIdx.x;
    const float* x = in + (size_t)t * HID;
    float ss = 0.f;
    for (int i = threadIdx.x; i < HID; i += 256) { float v = x[i]; ss += v * v; }
#pragma unroll
    for (int o = 16; o; o >>= 1) ss += __shfl_xor_sync(0xffffffffu, ss, o);
    __shared__ float red[8];
    __shared__ float stot;
    if ((threadIdx.x & 31) == 0) red[threadIdx.x >> 5] = ss;
    __syncthreads();
    if (threadIdx.x == 0) {
        float s = 0.f;
#pragma unroll
        for (int i = 0; i < 8; i++) s += red[i];
        stot = rsqrtf(s * (1.f / HID) + 1e-6f);
    }
    __syncthreads();
    float sc = stot;
    for (int i = threadIdx.x; i < HID; i += 256) {
        float v = x[i] * sc * w[i];
        if (outf) outf[(size_t)t * HID + i] = v;
        if (outb) outb[(size_t)t * HID + i] = __float2bfloat16(v);
    }
}

// ---------------------------------------------------------------------------
// Dense bf16 GEMM
// ---------------------------------------------------------------------------
__global__ void __launch_bounds__(256) k_gemm_bf16(
        const __nv_bfloat16* __restrict__ A, const float* __restrict__ B,
        float* __restrict__ C, const float* __restrict__ R,
        int M, int N, int K) {
    __shared__ __nv_bfloat16 As[2][BM * LDA_S];
    __shared__ __nv_bfloat16 Bs[2][BK * LDB_S];
    int tid = threadIdx.x;
    int warp = tid >> 5;
    int wm = warp & 3, wn = warp >> 2;
    int m0 = blockIdx.y * BM, n0 = blockIdx.x * BN;

    int a_r = tid >> 2, a_c = (tid & 3) * 8;
    int b_r = tid >> 4, b_c = (tid & 15) * 8;

    FragC acc[2][4];
    if (R) {
#pragma unroll
        for (int i = 0; i < 2; i++)
#pragma unroll
            for (int j = 0; j < 4; j++)
                wmma::load_matrix_sync(acc[i][j],
                    R + (size_t)(m0 + wm * 32 + i * 16) * N + n0 + wn * 64 + j * 16,
                    N, wmma::mem_row_major);
    } else {
#pragma unroll
        for (int i = 0; i < 2; i++)
#pragma unroll
            for (int j = 0; j < 4; j++) wmma::fill_fragment(acc[i][j], 0.f);
    }

    uint4 ra0, ra1;
    float4 rb0a, rb0b, rb1a, rb1b;
    auto ldg = [&](int k0) {
        ra0 = *(const uint4*)&A[(size_t)(m0 + a_r) * K + k0 + a_c];
        ra1 = *(const uint4*)&A[(size_t)(m0 + a_r + 64) * K + k0 + a_c];
        const float* p0 = &B[(size_t)(k0 + b_r) * N + n0 + b_c];
        rb0a = *(const float4*)p0; rb0b = *(const float4*)(p0 + 4);
        const float* p1 = &B[(size_t)(k0 + b_r + 16) * N + n0 + b_c];
        rb1a = *(const float4*)p1; rb1b = *(const float4*)(p1 + 4);
    };
    auto sts = [&](int buf) {
        *(uint4*)&As[buf][a_r * LDA_S + a_c] = ra0;
        *(uint4*)&As[buf][(a_r + 64) * LDA_S + a_c] = ra1;
        *(uint4*)&Bs[buf][b_r * LDB_S + b_c] = f8_to_bf8(rb0a, rb0b);
        *(uint4*)&Bs[buf][(b_r + 16) * LDB_S + b_c] = f8_to_bf8(rb1a, rb1b);
    };

    int niter = K / BK;
    ldg(0); sts(0); __syncthreads();
    for (int it = 0; it < niter; it++) {
        if (it + 1 < niter) ldg((it + 1) * BK);
        mma_tile(As[it & 1], Bs[it & 1], acc, wm, wn);
        if (it + 1 < niter) { sts((it + 1) & 1); __syncthreads(); }
    }
#pragma unroll
    for (int i = 0; i < 2; i++)
#pragma unroll
        for (int j = 0; j < 4; j++)
            wmma::store_matrix_sync(
                C + (size_t)(m0 + wm * 32 + i * 16) * N + n0 + wn * 64 + j * 16,
                acc[i][j], N, wmma::mem_row_major);
}

// ---------------------------------------------------------------------------
// Per-head RMSNorm + RoPE (q,k) and copy (v) -> bf16 buffers
// grid (NH + 2*NKV, T), block 32
// ---------------------------------------------------------------------------
__global__ void k_qk_prep(const int* __restrict__ pos,
                          const float* __restrict__ qnw,
                          const float* __restrict__ knw) {
    int hh = blockIdx.x;
    int t  = blockIdx.y;
    int i  = threadIdx.x;
    if (hh >= NH + NKV) {   // v: plain copy to bf16
        int vh = hh - NH - NKV;
        const float* src = g_qkv + (size_t)t * QKV_N + (NH + NKV) * HD + vh * HD;
        __nv_bfloat16* dst = g_vb + (size_t)t * (NKV * HD) + vh * HD;
        dst[i]      = __float2bfloat16(src[i]);
        dst[i + 32] = __float2bfloat16(src[i + 32]);
        return;
    }
    const float* src; __nv_bfloat16* dst; const float* w;
    if (hh < NH) {
        src = g_qkv + (size_t)t * QKV_N + hh * HD;
        dst = g_qb  + (size_t)t * (NH * HD) + hh * HD;
        w = qnw;
    } else {
        int kh = hh - NH;
        src = g_qkv + (size_t)t * QKV_N + NH * HD + kh * HD;
        dst = g_kb  + (size_t)t * (NKV * HD) + kh * HD;
        w = knw;
    }
    float x1 = src[i], x2 = src[i + 32];
    float ss = x1 * x1 + x2 * x2;
#pragma unroll
    for (int o = 16; o; o >>= 1) ss += __shfl_xor_sync(0xffffffffu, ss, o);
    float sc = rsqrtf(ss * (1.f / 64.f) + 1e-6f);
    x1 *= sc * w[i];
    x2 *= sc * w[i + 32];
    float p = (float)pos[t];
    float inv = powf(10000.f, -(float)i * (1.f / 32.f));
    float f = p * inv;
    float c = cosf(f), s = sinf(f);
    dst[i]      = __float2bfloat16(x1 * c - x2 * s);
    dst[i + 32] = __float2bfloat16(x2 * c + x1 * s);
}

// ---------------------------------------------------------------------------
// Flash attention, bf16 WMMA. grid (16 qtiles, 16 heads), 128 threads (4 warps).
// Per warp: 16 rows of the 64-row q tile. S staged fp32 in smem; softmax SIMT
// (2 threads/row); P bf16; O accumulated fp32 in smem via fragment add.
// ---------------------------------------------------------------------------
__global__ void __launch_bounds__(128) k_attn_wmma() {
    extern __shared__ char smraw[];
    __nv_bfloat16* Qs = (__nv_bfloat16*)smraw;            // 64*LDH
    __nv_bfloat16* Ks = Qs + 64 * LDH;
    __nv_bfloat16* Vs = Ks + 64 * LDH;
    __nv_bfloat16* Ps = Vs + 64 * LDH;
    float* Ss   = (float*)(Ps + 64 * LDH);                // 64*LDF
    float* Os   = Ss + 64 * LDF;                          // 64*LDF
    float* mrow = Os + 64 * LDF;                          // 64
    float* lrow = mrow + 64;                              // 64
    float* red1 = lrow + 64;                              // 128
    float* red2 = red1 + 128;                             // 128

    int h   = blockIdx.y;
    int m0  = blockIdx.x * 64;
    int kvh = h >> 2;
    int tid  = threadIdx.x;
    int warp = tid >> 5;

    // load Q tile (bf16)
#pragma unroll
    for (int j = 0; j < 4; j++) {
        int idx = tid + j * 128;
        int r = idx >> 3, c = (idx & 7) * 8;
        *(uint4*)&Qs[r * LDH + c] =
            *(const uint4*)&g_qb[(size_t)(m0 + r) * (NH * HD) + h * HD + c];
    }
    for (int i = tid; i < 64 * LDF; i += 128) Os[i] = 0.f;
    if (tid < 64) { mrow[tid] = -INFINITY; lrow[tid] = 0.f; }

    int row  = tid & 63;
    int half = tid >> 6;
    int c0   = half * 32;
    int rglob = m0 + row;

    int ntiles = (m0 >> 6) + 1;
    for (int nt = 0; nt < ntiles; nt++) {
        int n0 = nt * 64;
        __syncthreads();   // protect Ks/Vs from previous iteration readers
        // load K, V tiles
#pragma unroll
        for (int j = 0; j < 4; j++) {
            int idx = tid + j * 128;
            int r = idx >> 3, c = (idx & 7) * 8;
            *(uint4*)&Ks[r * LDH + c] =
                *(const uint4*)&g_kb[(size_t)(n0 + r) * (NKV * HD) + kvh * HD + c];
            *(uint4*)&Vs[r * LDH + c] =
                *(const uint4*)&g_vb[(size_t)(n0 + r) * (NKV * HD) + kvh * HD + c];
        }
        __syncthreads();

        // S = Q @ K^T  (per warp: 16 rows x 64 cols)
#pragma unroll
        for (int n = 0; n < 4; n++) {
            FragC s;
            wmma::fill_fragment(s, 0.f);
#pragma unroll
            for (int k = 0; k < 4; k++) {
                FragA a;
                FragBc b;
                wmma::load_matrix_sync(a, Qs + (warp * 16) * LDH + k * 16, LDH);
                wmma::load_matrix_sync(b, Ks + (n * 16) * LDH + k * 16, LDH);
                wmma::mma_sync(s, a, b, s);
            }
            wmma::store_matrix_sync(Ss + (warp * 16) * LDF + n * 16, s, LDF,
                                    wmma::mem_row_major);
        }
        __syncthreads();

        // softmax pass 1: half-row max (with causal mask)
        float mx = -INFINITY;
#pragma unroll
        for (int c = 0; c < 32; c++) {
            int cg = n0 + c0 + c;
            float v = (cg <= rglob) ? Ss[row * LDF + c0 + c] * 0.125f : -INFINITY;
            mx = fmaxf(mx, v);
        }
        red1[row * 2 + half] = mx;
        __syncthreads();

        // softmax pass 2: exp, write P (bf16), half-row sum, rescale O
        float tmax = fmaxf(red1[row * 2], red1[row * 2 + 1]);
        float mold = mrow[row];
        float mn = fmaxf(mold, tmax);
        float alpha = __expf(mold - mn);
        float ps = 0.f;
#pragma unroll
        for (int c = 0; c < 32; c++) {
            int cg = n0 + c0 + c;
            float p = (cg <= rglob) ? __expf(Ss[row * LDF + c0 + c] * 0.125f - mn) : 0.f;
            Ps[row * LDH + c0 + c] = __float2bfloat16(p);
            ps += p;
        }
        red2[row * 2 + half] = ps;
#pragma unroll
        for (int c = 0; c < 32; c++) Os[row * LDF + c0 + c] *= alpha;
        __syncthreads();
        if (half == 0) {
            lrow[row] = lrow[row] * alpha + red2[row * 2] + red2[row * 2 + 1];
            mrow[row] = mn;
        }

        // O += P @ V  (per warp, fragment-level accumulate on Os)
#pragma unroll
        for (int n = 0; n < 4; n++) {
            FragC acc;
            wmma::fill_fragment(acc, 0.f);
#pragma unroll
            for (int k = 0; k < 4; k++) {
                FragA a;
                FragB b;
                wmma::load_matrix_sync(a, Ps + (warp * 16) * LDH + k * 16, LDH);
                wmma::load_matrix_sync(b, Vs + (k * 16) * LDH + n * 16, LDH);
                wmma::mma_sync(acc, a, b, acc);
            }
            FragC o;
            wmma::load_matrix_sync(o, Os + (warp * 16) * LDF + n * 16, LDF,
                                   wmma::mem_row_major);
#pragma unroll
            for (int e = 0; e < o.num_elements; e++) o.x[e] += acc.x[e];
            wmma::store_matrix_sync(Os + (warp * 16) * LDF + n * 16, o, LDF,
                                    wmma::mem_row_major);
        }
    }
    __syncthreads();

    // epilogue: normalize and write bf16
    float inv = 1.f / lrow[row];
#pragma unroll
    for (int c = 0; c < 32; c++)
        g_attnb[(size_t)(m0 + row) * (NH * HD) + h * HD + c0 + c] =
            __float2bfloat16(Os[row * LDF + c0 + c] * inv);
}

// ---------------------------------------------------------------------------
// Routing
// ---------------------------------------------------------------------------
__global__ void k_zero() {
    int i = threadIdx.x;
    if (i < NE) { g_cnt[i] = 0; g_fill[i] = 0; }
}

__global__ void k_route(const float* __restrict__ H2, const float* __restrict__ Wg) {
    int t = blockIdx.x;
    int e = threadIdx.x;
    __shared__ float sh[HID];
    for (int i = e; i < HID; i += 64) sh[i] = H2[(size_t)t * HID + i];
    __syncthreads();
    float a0 = 0, a1 = 0, a2 = 0, a3 = 0;
    for (int k = 0; k < HID; k += 4) {
        a0 += sh[k]     * Wg[(size_t)k       * NE + e];
        a1 += sh[k + 1] * Wg[(size_t)(k + 1) * NE + e];
        a2 += sh[k + 2] * Wg[(size_t)(k + 2) * NE + e];
        a3 += sh[k + 3] * Wg[(size_t)(k + 3) * NE + e];
    }
    __shared__ float logits[NE];
    logits[e] = (a0 + a1) + (a2 + a3);
    __syncthreads();
    if (e == 0) {
        float sv[NG]; int si[NG];
#pragma unroll
        for (int g = 0; g < NG; g++) {
            float best = logits[g * 8]; int bi = g * 8;
#pragma unroll
            for (int j = 1; j < 8; j++) {
                float v = logits[g * 8 + j];
                if (v > best) { best = v; bi = g * 8 + j; }
            }
            sv[g] = best; si[g] = bi;
        }
        float m = sv[0];
#pragma unroll
        for (int g = 1; g < NG; g++) m = fmaxf(m, sv[g]);
        float sum = 0.f, p[NG];
#pragma unroll
        for (int g = 0; g < NG; g++) { p[g] = expf(sv[g] - m); sum += p[g]; }
        float is = 1.f / sum;
#pragma unroll
        for (int g = 0; g < NG; g++) {
            g_selid[t * NG + g] = si[g];
            g_selw [t * NG + g] = p[g] * is;
            atomicAdd(&g_cnt[si[g]], 1);
        }
    }
}

__global__ void k_scan() {
    int s = 0;
    for (int e = 0; e < NE; e++) { g_off[e] = s; s += (g_cnt[e] + BM - 1) & ~(BM - 1); }
}

__global__ void k_scatter() {
    int t = blockIdx.x, g = threadIdx.x;
    int e = g_selid[t * NG + g];
    int slot = atomicAdd(&g_fill[e], 1);
    int row = g_off[e] + slot;
    g_tok[row] = t;
    g_w[row]   = g_selw[t * NG + g];
}

// ---------------------------------------------------------------------------
// MoE GEMM 1 (bf16)
// ---------------------------------------------------------------------------
__global__ void __launch_bounds__(256) k_moe1(const __nv_bfloat16* __restrict__ Ab,
                                              const float* __restrict__ Wgu) {
    int e = blockIdx.z;
    int cnt = g_cnt[e];
    int m0 = blockIdx.y * BM;
    if (m0 >= cnt) return;
    int off = g_off[e];
    int n0 = blockIdx.x * BN;
    const float* B = Wgu + (size_t)e * (HID * 1024);

    __shared__ __nv_bfloat16 As[2][BM * LDA_S];
    __shared__ __nv_bfloat16 Bs[2][BK * LDB_S];
    __shared__ int stok[BM];
    int tid = threadIdx.x;
    int warp = tid >> 5;
    int wm = warp & 3, wn = warp >> 2;
    if (tid < BM) stok[tid] = (m0 + tid < cnt) ? g_tok[off + m0 + tid] : -1;
    __syncthreads();

    int a_r = tid >> 2, a_c = (tid & 3) * 8;
    int b_r = tid >> 4, b_c = (tid & 15) * 8;
    int tk0 = stok[a_r], tk1 = stok[a_r + 64];

    FragC acc[2][4];
#pragma unroll
    for (int i = 0; i < 2; i++)
#pragma unroll
        for (int j = 0; j < 4; j++) wmma::fill_fragment(acc[i][j], 0.f);

    uint4 ra0, ra1;
    float4 rb0a, rb0b, rb1a, rb1b;
    const uint4 Z = make_uint4(0, 0, 0, 0);
    auto ldg = [&](int k0) {
        ra0 = (tk0 >= 0) ? *(const uint4*)&Ab[(size_t)tk0 * HID + k0 + a_c] : Z;
        ra1 = (tk1 >= 0) ? *(const uint4*)&Ab[(size_t)tk1 * HID + k0 + a_c] : Z;
        const float* p0 = &B[(size_t)(k0 + b_r) * 1024 + n0 + b_c];
        rb0a = *(const float4*)p0; rb0b = *(const float4*)(p0 + 4);
        const float* p1 = &B[(size_t)(k0 + b_r + 16) * 1024 + n0 + b_c];
        rb1a = *(const float4*)p1; rb1b = *(const float4*)(p1 + 4);
    };
    auto sts = [&](int buf) {
        *(uint4*)&As[buf][a_r * LDA_S + a_c] = ra0;
        *(uint4*)&As[buf][(a_r + 64) * LDA_S + a_c] = ra1;
        *(uint4*)&Bs[buf][b_r * LDB_S + b_c] = f8_to_bf8(rb0a, rb0b);
        *(uint4*)&Bs[buf][(b_r + 16) * LDB_S + b_c] = f8_to_bf8(rb1a, rb1b);
    };

    const int niter = HID / BK;
    ldg(0); sts(0); __syncthreads();
    for (int it = 0; it < niter; it++) {
        if (it + 1 < niter) ldg((it + 1) * BK);
        mma_tile(As[it & 1], Bs[it & 1], acc, wm, wn);
        if (it + 1 < niter) { sts((it + 1) & 1); __syncthreads(); }
    }
#pragma unroll
    for (int i = 0; i < 2; i++)
#pragma unroll
        for (int j = 0; j < 4; j++)
            wmma::store_matrix_sync(
                g_gu + (size_t)(off + m0 + wm * 32 + i * 16) * 1024 + n0 + wn * 64 + j * 16,
                acc[i][j], 1024, wmma::mem_row_major);
}

// act[row,i] = silu(g)*u*w -> bf16
__global__ void k_moe_act() {
    int idx = blockIdx.x * 256 + threadIdx.x;
    int r  = idx >> 7;
    int i4 = (idx & 127) * 4;
    float4 g = *(const float4*)&g_gu[(size_t)r * 1024 + i4];
    float4 u = *(const float4*)&g_gu[(size_t)r * 1024 + 512 + i4];
    float w = g_w[r];
    float s0 = g.x / (1.f + __expf(-g.x)) * u.x * w;
    float s1 = g.y / (1.f + __expf(-g.y)) * u.y * w;
    float s2 = g.z / (1.f + __expf(-g.z)) * u.z * w;
    float s3 = g.w / (1.f + __expf(-g.w)) * u.w * w;
    __nv_bfloat162 p0 = __floats2bfloat162_rn(s0, s1);
    __nv_bfloat162 p1 = __floats2bfloat162_rn(s2, s3);
    uint2 v;
    v.x = *reinterpret_cast<unsigned*>(&p0);
    v.y = *reinterpret_cast<unsigned*>(&p1);
    *(uint2*)&g_actb[(size_t)r * INTER + i4] = v;
}

// ---------------------------------------------------------------------------
// MoE GEMM 2 (bf16) with staged scatter-add
// ---------------------------------------------------------------------------
__global__ void __launch_bounds__(256) k_moe2(const float* __restrict__ Wd,
                                              float* __restrict__ out) {
    int e = blockIdx.z;
    int cnt = g_cnt[e];
    int m0 = blockIdx.y * BM;
    if (m0 >= cnt) return;
    int off = g_off[e];
    int n0 = blockIdx.x * BN;
    const float* B = Wd + (size_t)e * (INTER * HID);

    __shared__ __nv_bfloat16 As[2][BM * LDA_S];
    __shared__ __nv_bfloat16 Bs[2][BK * LDB_S];
    __shared__ float stage[8 * 272];
    __shared__ int stok[BM];
    int tid = threadIdx.x;
    int lane = tid & 31;
    int warp = tid >> 5;
    int wm = warp & 3, wn = warp >> 2;
    if (tid < BM) stok[tid] = (m0 + tid < cnt) ? g_tok[off + m0 + tid] : -1;
    __syncthreads();

    int a_r = tid >> 2, a_c = (tid & 3) * 8;
    int b_r = tid >> 4, b_c = (tid & 15) * 8;

    FragC acc[2][4];
#pragma unroll
    for (int i = 0; i < 2; i++)
#pragma unroll
        for (int j = 0; j < 4; j++) wmma::fill_fragment(acc[i][j], 0.f);

    uint4 ra0, ra1;
    float4 rb0a, rb0b, rb1a, rb1b;
    auto ldg = [&](int k0) {
        ra0 = *(const uint4*)&g_actb[(size_t)(off + m0 + a_r) * INTER + k0 + a_c];
        ra1 = *(const uint4*)&g_actb[(size_t)(off + m0 + a_r + 64) * INTER + k0 + a_c];
        const float* p0 = &B[(size_t)(k0 + b_r) * HID + n0 + b_c];
        rb0a = *(const float4*)p0; rb0b = *(const float4*)(p0 + 4);
        const float* p1 = &B[(size_t)(k0 + b_r + 16) * HID + n0 + b_c];
        rb1a = *(const float4*)p1; rb1b = *(const float4*)(p1 + 4);
    };
    auto sts = [&](int buf) {
        *(uint4*)&As[buf][a_r * LDA_S + a_c] = ra0;
        *(uint4*)&As[buf][(a_r + 64) * LDA_S + a_c] = ra1;
        *(uint4*)&Bs[buf][b_r * LDB_S + b_c] = f8_to_bf8(rb0a, rb0b);
        *(uint4*)&Bs[buf][(b_r + 16) * LDB_S + b_c] = f8_to_bf8(rb1a, rb1b);
    };

    const int niter = INTER / BK;
    ldg(0); sts(0); __syncthreads();
    for (int it = 0; it < niter; it++) {
        if (it + 1 < niter) ldg((it + 1) * BK);
        mma_tile(As[it & 1], Bs[it & 1], acc, wm, wn);
        if (it + 1 < niter) { sts((it + 1) & 1); __syncthreads(); }
    }

#pragma unroll
    for (int i = 0; i < 2; i++) {
#pragma unroll
        for (int j = 0; j < 4; j++) {
            wmma::store_matrix_sync(&stage[warp * 272], acc[i][j], 16, wmma::mem_row_major);
            __syncwarp();
#pragma unroll
            for (int q = 0; q < 8; q++) {
                int el = lane + q * 32;
                int r = el >> 4, c = el & 15;
                int lr = wm * 32 + i * 16 + r;
                if (m0 + lr < cnt) {
                    int tk = stok[lr];
                    atomicAdd(&out[(size_t)tk * HID + n0 + wn * 64 + j * 16 + c],
                              stage[warp * 272 + r * 16 + c]);
                }
            }
            __syncwarp();
        }
    }
}

// ---------------------------------------------------------------------------
// Launch
// ---------------------------------------------------------------------------
extern "C" void kernel_launch(void* const* d_in, const int* in_sizes, int n_in,
                              void* d_out, int out_size) {
    const int*   positions = (const int*)  d_in[0];
    const float* hidden    = (const float*)d_in[1];
    const float* Wqkv      = (const float*)d_in[2];
    const float* Wo        = (const float*)d_in[3];
    const float* qnw       = (const float*)d_in[4];
    const float* knw       = (const float*)d_in[5];
    const float* inln      = (const float*)d_in[6];
    const float* postln    = (const float*)d_in[7];
    const float* Wg        = (const float*)d_in[8];
    const float* Wgu       = (const float*)d_in[9];
    const float* Wd        = (const float*)d_in[10];
    float* out = (float*)d_out;

    __nv_bfloat16 *p_hb, *p_attnb, *p_h2b;
    float *p_qkv, *p_h2;
    cudaGetSymbolAddress((void**)&p_hb,    g_hb);
    cudaGetSymbolAddress((void**)&p_qkv,   g_qkv);
    cudaGetSymbolAddress((void**)&p_h2,    g_h2);
    cudaGetSymbolAddress((void**)&p_h2b,   g_h2b);
    cudaGetSymbolAddress((void**)&p_attnb, g_attnb);

    // attention dynamic smem: 4 bf16 tiles + 2 fp32 tiles + reductions
    const int ATTN_SMEM = (4 * 64 * LDH) * 2 + (2 * 64 * LDF) * 4 + (64 + 64 + 128 + 128) * 4;
    cudaFuncSetAttribute(k_attn_wmma, cudaFuncAttributeMaxDynamicSharedMemorySize, ATTN_SMEM);

    // 1. pre-attn rmsnorm (bf16)
    k_rmsnorm<<<T_TOK, 256>>>(hidden, inln, nullptr, p_hb);
    // 2. qkv projection
    k_gemm_bf16<<<dim3(QKV_N / BN, T_TOK / BM), 256>>>(p_hb, Wqkv, p_qkv, nullptr,
                                                       T_TOK, QKV_N, HID);
    // 3. per-head rmsnorm + rope + v convert (all -> bf16)
    k_qk_prep<<<dim3(NH + 2 * NKV, T_TOK), 32>>>(positions, qnw, knw);
    // 4. causal flash attention (bf16 WMMA)
    k_attn_wmma<<<dim3(T_TOK / 64, NH), 128, ATTN_SMEM>>>();
    // 5. x = resid + attn @ Wo
    k_gemm_bf16<<<dim3(HID / BN, T_TOK / BM), 256>>>(p_attnb, Wo, out, hidden,
                                                     T_TOK, HID, NH * HD);
    // 6. post-attn rmsnorm
    k_rmsnorm<<<T_TOK, 256>>>(out, postln, p_h2, p_h2b);
    // 7-10. routing
    k_zero<<<1, 64>>>();
    k_route<<<T_TOK, 64>>>(p_h2, Wg);
    k_scan<<<1, 1>>>();
    k_scatter<<<T_TOK, 8>>>();
    // 11. grouped gate_up GEMM
    k_moe1<<<dim3(1024 / BN, 8, NE), 256>>>(p_h2b, Wgu);
    // 12. silu(g)*u*w -> bf16
    k_moe_act<<<(NA_PAD * 128) / 256, 256>>>();
    // 13. grouped down GEMM, scatter-add into d_out
    k_moe2<<<dim3(HID / BN, 8, NE), 256>>>(Wd, out);
}